// round 4
// baseline (speedup 1.0000x reference)
#include <cuda_runtime.h>
#include <cuda_bf16.h>

// Problem constants
#define BATCH 2
#define NTOK 4096
#define CDIM 1024
#define HEADS 16
#define HDIM 64
#define MROWS (BATCH * NTOK)          // 8192
#define QKVN (3 * CDIM)               // 3072
#define PER_HEAD_ELEMS (BATCH * HEADS * NTOK * HDIM)  // 8,388,608

// Scratch (static __device__ — no allocation allowed)
__device__ float g_q[PER_HEAD_ELEMS];
__device__ float g_k[PER_HEAD_ELEMS];
__device__ float g_v[PER_HEAD_ELEMS];
__device__ float g_o[MROWS * CDIM];

// ---------------------------------------------------------------------------
// Kernel 1: QKV GEMM (TN: both operands K-contiguous) + bias + fused per-head
// LayerNorm on q,k (+ fold in D^-0.5 scale for q). Tile 64x64, BK=16, 256 thr,
// 4x4 per thread. Output scattered into [B,H,N,D] per-part buffers.
// ---------------------------------------------------------------------------
__global__ __launch_bounds__(256) void qkv_gemm_kernel(
    const float* __restrict__ X,      // [8192,1024]
    const float* __restrict__ W,      // [3072,1024]
    const float* __restrict__ bias,   // [3072]
    const float* __restrict__ qnw, const float* __restrict__ qnb,
    const float* __restrict__ knw, const float* __restrict__ knb)
{
    __shared__ float As[16][68];   // k-major transposed: As[k][m]
    __shared__ float Bs[16][68];

    const int tid = threadIdx.x;
    const int tx = tid & 15, ty = tid >> 4;
    const int row0 = blockIdx.y * 64;
    const int col0 = blockIdx.x * 64;

    const int lr = tid >> 2;            // 0..63 (tile row)
    const int lk = (tid & 3) << 2;      // 0,4,8,12 (k offset)
    const float* Aptr = X + (size_t)(row0 + lr) * CDIM + lk;
    const float* Bptr = W + (size_t)(col0 + lr) * CDIM + lk;

    float acc[4][4] = {};

    for (int k0 = 0; k0 < CDIM; k0 += 16) {
        float4 a4 = *(const float4*)(Aptr + k0);
        float4 b4 = *(const float4*)(Bptr + k0);
        As[lk + 0][lr] = a4.x; As[lk + 1][lr] = a4.y;
        As[lk + 2][lr] = a4.z; As[lk + 3][lr] = a4.w;
        Bs[lk + 0][lr] = b4.x; Bs[lk + 1][lr] = b4.y;
        Bs[lk + 2][lr] = b4.z; Bs[lk + 3][lr] = b4.w;
        __syncthreads();
        #pragma unroll
        for (int kk = 0; kk < 16; kk++) {
            float4 av = *(const float4*)&As[kk][ty * 4];
            float4 bv = *(const float4*)&Bs[kk][tx * 4];
            float a[4] = {av.x, av.y, av.z, av.w};
            float b[4] = {bv.x, bv.y, bv.z, bv.w};
            #pragma unroll
            for (int i = 0; i < 4; i++)
                #pragma unroll
                for (int j = 0; j < 4; j++)
                    acc[i][j] += a[i] * b[j];
        }
        __syncthreads();
    }

    // epilogue: bias + (LN for q/k)
    const int part = col0 >> 10;            // 0=q,1=k,2=v (uniform per block)
    const int c = col0 & 1023;
    const int h = c >> 6;

    float vres[4][4];
    #pragma unroll
    for (int i = 0; i < 4; i++)
        #pragma unroll
        for (int j = 0; j < 4; j++)
            vres[i][j] = acc[i][j] + bias[col0 + tx * 4 + j];

    if (part < 2) {
        const float* nw = (part == 0) ? qnw : knw;
        const float* nb = (part == 0) ? qnb : knb;
        const float sc = (part == 0) ? 0.125f : 1.0f;   // D^-0.5 = 1/8
        #pragma unroll
        for (int i = 0; i < 4; i++) {
            float s = vres[i][0] + vres[i][1] + vres[i][2] + vres[i][3];
            #pragma unroll
            for (int o = 8; o >= 1; o >>= 1)
                s += __shfl_xor_sync(0xffffffffu, s, o, 16);
            float mean = s * (1.0f / 64.0f);
            float sq = 0.f;
            #pragma unroll
            for (int j = 0; j < 4; j++) {
                float d0 = vres[i][j] - mean;
                sq += d0 * d0;
            }
            #pragma unroll
            for (int o = 8; o >= 1; o >>= 1)
                sq += __shfl_xor_sync(0xffffffffu, sq, o, 16);
            float inv = rsqrtf(sq * (1.0f / 64.0f) + 1e-5f);
            #pragma unroll
            for (int j = 0; j < 4; j++) {
                int d = tx * 4 + j;
                vres[i][j] = ((vres[i][j] - mean) * inv * nw[d] + nb[d]) * sc;
            }
        }
    }

    float* dst = (part == 0) ? g_q : (part == 1) ? g_k : g_v;
    #pragma unroll
    for (int i = 0; i < 4; i++) {
        int m = row0 + ty * 4 + i;
        int bb = m >> 12, t = m & 4095;
        float* p = dst + (((size_t)(bb * HEADS + h) * NTOK + t) * HDIM) + tx * 4;
        *(float4*)p = make_float4(vres[i][0], vres[i][1], vres[i][2], vres[i][3]);
    }
}

// ---------------------------------------------------------------------------
// Kernel 2: flash attention. Block = 64 queries, loop over 64-key tiles with
// online softmax. fp32, q pre-scaled. 256 thr, 4x4 per thread.
// smem: Qt/Kt [d][tok] 64x68, Vs [tok][d] 64x68, Ps [row][key] 64x68.
// ---------------------------------------------------------------------------
__global__ __launch_bounds__(256) void flash_kernel()
{
    extern __shared__ float sm[];
    float* Qt = sm;                  // [64][68]  d-major
    float* Kt = Qt + 64 * 68;        // [64][68]  d-major
    float* Vs = Kt + 64 * 68;        // [64][68]  key-major
    float* Ps = Vs + 64 * 68;        // [64][68]  row-major

    const int tid = threadIdx.x;
    const int tx = tid & 15, ty = tid >> 4;
    const int qb = blockIdx.x;       // 0..63
    const int bh = blockIdx.y;       // 0..31

    const float* Qg = g_q + (size_t)bh * NTOK * HDIM + (size_t)qb * 64 * HDIM;
    const float* Kg = g_k + (size_t)bh * NTOK * HDIM;
    const float* Vg = g_v + (size_t)bh * NTOK * HDIM;

    // load Q tile transposed (coalesced: linear idx over 1024 float4s)
    #pragma unroll
    for (int it = 0; it < 4; it++) {
        int idx = it * 256 + tid;
        int r = idx >> 4;
        int d4 = (idx & 15) * 4;
        float4 v = *(const float4*)(Qg + r * HDIM + d4);
        Qt[(d4 + 0) * 68 + r] = v.x;
        Qt[(d4 + 1) * 68 + r] = v.y;
        Qt[(d4 + 2) * 68 + r] = v.z;
        Qt[(d4 + 3) * 68 + r] = v.w;
    }

    float m_i[4], l_i[4], o[4][4];
    #pragma unroll
    for (int i = 0; i < 4; i++) {
        m_i[i] = -1e30f;
        l_i[i] = 0.f;
        #pragma unroll
        for (int j = 0; j < 4; j++) o[i][j] = 0.f;
    }

    for (int k0 = 0; k0 < NTOK; k0 += 64) {
        // load K (transposed) + V tiles
        #pragma unroll
        for (int it = 0; it < 4; it++) {
            int idx = it * 256 + tid;
            int r = idx >> 4;
            int d4 = (idx & 15) * 4;
            float4 kv = *(const float4*)(Kg + (k0 + r) * HDIM + d4);
            Kt[(d4 + 0) * 68 + r] = kv.x;
            Kt[(d4 + 1) * 68 + r] = kv.y;
            Kt[(d4 + 2) * 68 + r] = kv.z;
            Kt[(d4 + 3) * 68 + r] = kv.w;
            float4 vv = *(const float4*)(Vg + (k0 + r) * HDIM + d4);
            *(float4*)&Vs[r * 68 + d4] = vv;
        }
        __syncthreads();

        // S = Q K^T  (q already scaled)
        float s[4][4] = {};
        #pragma unroll 8
        for (int d = 0; d < 64; d++) {
            float4 av = *(const float4*)&Qt[d * 68 + ty * 4];
            float4 bv = *(const float4*)&Kt[d * 68 + tx * 4];
            float a[4] = {av.x, av.y, av.z, av.w};
            float b[4] = {bv.x, bv.y, bv.z, bv.w};
            #pragma unroll
            for (int i = 0; i < 4; i++)
                #pragma unroll
                for (int j = 0; j < 4; j++)
                    s[i][j] += a[i] * b[j];
        }

        // online softmax (row group = 16 lanes sharing ty)
        #pragma unroll
        for (int i = 0; i < 4; i++) {
            float mx = fmaxf(fmaxf(s[i][0], s[i][1]), fmaxf(s[i][2], s[i][3]));
            #pragma unroll
            for (int od = 8; od >= 1; od >>= 1)
                mx = fmaxf(mx, __shfl_xor_sync(0xffffffffu, mx, od, 16));
            float mnew = fmaxf(m_i[i], mx);
            float alpha = __expf(m_i[i] - mnew);
            m_i[i] = mnew;
            float rs = 0.f;
            #pragma unroll
            for (int j = 0; j < 4; j++) {
                s[i][j] = __expf(s[i][j] - mnew);
                rs += s[i][j];
            }
            #pragma unroll
            for (int od = 8; od >= 1; od >>= 1)
                rs += __shfl_xor_sync(0xffffffffu, rs, od, 16);
            l_i[i] = l_i[i] * alpha + rs;
            #pragma unroll
            for (int j = 0; j < 4; j++) o[i][j] *= alpha;
            *(float4*)&Ps[(ty * 4 + i) * 68 + tx * 4] =
                make_float4(s[i][0], s[i][1], s[i][2], s[i][3]);
        }
        __syncthreads();

        // O += P @ V
        #pragma unroll 8
        for (int kk = 0; kk < 64; kk++) {
            float4 bv = *(const float4*)&Vs[kk * 68 + tx * 4];
            #pragma unroll
            for (int i = 0; i < 4; i++) {
                float a = Ps[(ty * 4 + i) * 68 + kk];
                o[i][0] += a * bv.x;
                o[i][1] += a * bv.y;
                o[i][2] += a * bv.z;
                o[i][3] += a * bv.w;
            }
        }
        __syncthreads();
    }

    // write O in [B,N,H*D] layout
    const int hh = bh & 15, bb2 = bh >> 4;
    #pragma unroll
    for (int i = 0; i < 4; i++) {
        int t = qb * 64 + ty * 4 + i;
        float inv_l = 1.0f / l_i[i];
        float* p = g_o + ((size_t)(bb2 * NTOK + t) * CDIM) + hh * 64 + tx * 4;
        *(float4*)p = make_float4(o[i][0] * inv_l, o[i][1] * inv_l,
                                  o[i][2] * inv_l, o[i][3] * inv_l);
    }
}

// ---------------------------------------------------------------------------
// Kernel 3: output projection GEMM (TN) + bias -> d_out
// ---------------------------------------------------------------------------
__global__ __launch_bounds__(256) void proj_gemm_kernel(
    const float* __restrict__ W,      // [1024,1024]
    const float* __restrict__ bias,   // [1024]
    float* __restrict__ out)          // [8192,1024]
{
    __shared__ float As[16][68];
    __shared__ float Bs[16][68];

    const int tid = threadIdx.x;
    const int tx = tid & 15, ty = tid >> 4;
    const int row0 = blockIdx.y * 64;
    const int col0 = blockIdx.x * 64;

    const int lr = tid >> 2;
    const int lk = (tid & 3) << 2;
    const float* Aptr = g_o + (size_t)(row0 + lr) * CDIM + lk;
    const float* Bptr = W + (size_t)(col0 + lr) * CDIM + lk;

    float acc[4][4] = {};

    for (int k0 = 0; k0 < CDIM; k0 += 16) {
        float4 a4 = *(const float4*)(Aptr + k0);
        float4 b4 = *(const float4*)(Bptr + k0);
        As[lk + 0][lr] = a4.x; As[lk + 1][lr] = a4.y;
        As[lk + 2][lr] = a4.z; As[lk + 3][lr] = a4.w;
        Bs[lk + 0][lr] = b4.x; Bs[lk + 1][lr] = b4.y;
        Bs[lk + 2][lr] = b4.z; Bs[lk + 3][lr] = b4.w;
        __syncthreads();
        #pragma unroll
        for (int kk = 0; kk < 16; kk++) {
            float4 av = *(const float4*)&As[kk][ty * 4];
            float4 bv = *(const float4*)&Bs[kk][tx * 4];
            float a[4] = {av.x, av.y, av.z, av.w};
            float b[4] = {bv.x, bv.y, bv.z, bv.w};
            #pragma unroll
            for (int i = 0; i < 4; i++)
                #pragma unroll
                for (int j = 0; j < 4; j++)
                    acc[i][j] += a[i] * b[j];
        }
        __syncthreads();
    }

    #pragma unroll
    for (int i = 0; i < 4; i++) {
        int m = row0 + ty * 4 + i;
        int n = col0 + tx * 4;
        float* p = out + (size_t)m * CDIM + n;
        *(float4*)p = make_float4(acc[i][0] + bias[n + 0],
                                  acc[i][1] + bias[n + 1],
                                  acc[i][2] + bias[n + 2],
                                  acc[i][3] + bias[n + 3]);
    }
}

// ---------------------------------------------------------------------------
extern "C" void kernel_launch(void* const* d_in, const int* in_sizes, int n_in,
                              void* d_out, int out_size)
{
    const float* x     = (const float*)d_in[0];
    const float* qkv_w = (const float*)d_in[1];
    const float* qkv_b = (const float*)d_in[2];
    const float* qnw   = (const float*)d_in[3];
    const float* qnb   = (const float*)d_in[4];
    const float* knw   = (const float*)d_in[5];
    const float* knb   = (const float*)d_in[6];
    const float* pw    = (const float*)d_in[7];
    const float* pb    = (const float*)d_in[8];
    float* out = (float*)d_out;

    const int flash_smem = 4 * 64 * 68 * (int)sizeof(float);   // 69632 B
    cudaFuncSetAttribute(flash_kernel,
                         cudaFuncAttributeMaxDynamicSharedMemorySize, flash_smem);

    qkv_gemm_kernel<<<dim3(QKVN / 64, MROWS / 64), 256>>>(
        x, qkv_w, qkv_b, qnw, qnb, knw, knb);
    flash_kernel<<<dim3(NTOK / 64, BATCH * HEADS), 256, flash_smem>>>();
    proj_gemm_kernel<<<dim3(CDIM / 64, MROWS / 64), 256>>>(pw, pb, out);
}

// round 7
// speedup vs baseline: 2.7221x; 2.7221x over previous
#include <cuda_runtime.h>
#include <cuda_bf16.h>

#define BATCH 2
#define NTOK 4096
#define CDIM 1024
#define HEADS 16
#define HDIM 64
#define MROWS (BATCH * NTOK)          // 8192
#define QKVN (3 * CDIM)               // 3072
#define PHE (BATCH * HEADS * NTOK * HDIM)  // 8,388,608
#define STR 40                        // GEMM smem row stride (BK=32 rows + pad)
#define STRF 72                       // flash smem row stride (HDIM=64 rows + pad)

// ---- static scratch (no allocation allowed) ----
__device__ __align__(16) __nv_bfloat16 g_xh[MROWS * CDIM], g_xl[MROWS * CDIM];
__device__ __align__(16) __nv_bfloat16 g_wqh[QKVN * CDIM], g_wql[QKVN * CDIM];
__device__ __align__(16) __nv_bfloat16 g_wph[CDIM * CDIM], g_wpl[CDIM * CDIM];
__device__ __align__(16) __nv_bfloat16 g_qh[PHE], g_ql[PHE];
__device__ __align__(16) __nv_bfloat16 g_kh[PHE], g_kl[PHE];
__device__ __align__(16) __nv_bfloat16 g_vh[PHE], g_vl[PHE];
__device__ __align__(16) __nv_bfloat16 g_oh[MROWS * CDIM], g_ol[MROWS * CDIM];

__device__ __forceinline__ unsigned pack2(__nv_bfloat16 a, __nv_bfloat16 b) {
    __nv_bfloat162 t = __halves2bfloat162(a, b);   // a -> low 16 bits
    return *reinterpret_cast<unsigned*>(&t);
}

__device__ __forceinline__ void mma16816(float c[4], const unsigned a[4], const unsigned b[2]) {
    asm volatile(
        "mma.sync.aligned.m16n8k16.row.col.f32.bf16.bf16.f32 "
        "{%0,%1,%2,%3}, {%4,%5,%6,%7}, {%8,%9}, {%0,%1,%2,%3};\n"
        : "+f"(c[0]), "+f"(c[1]), "+f"(c[2]), "+f"(c[3])
        : "r"(a[0]), "r"(a[1]), "r"(a[2]), "r"(a[3]), "r"(b[0]), "r"(b[1]));
}

// ---------------------------------------------------------------------------
// fp32 -> bf16 hi/lo split (x, qkv_w, proj_w)
// ---------------------------------------------------------------------------
__global__ void convert_kernel(const float* __restrict__ src, int which, int n) {
    __nv_bfloat16 *h, *l;
    if (which == 0)      { h = g_xh;  l = g_xl;  }
    else if (which == 1) { h = g_wqh; l = g_wql; }
    else                 { h = g_wph; l = g_wpl; }
    for (int i = blockIdx.x * blockDim.x + threadIdx.x; i < n;
         i += gridDim.x * blockDim.x) {
        float x = src[i];
        __nv_bfloat16 hi = __float2bfloat16(x);
        h[i] = hi;
        l[i] = __float2bfloat16(x - __bfloat162float(hi));
    }
}

// ---------------------------------------------------------------------------
// QKV GEMM (bf16x3 split, mma.sync) + bias + fused per-head LN on q,k
// Block 128x128, BK=32, 256 thr, 8 warps as 4(m)x2(n), warp tile 32x64.
// ---------------------------------------------------------------------------
__global__ __launch_bounds__(256) void qkv_mma_kernel(
    const float* __restrict__ bias,
    const float* __restrict__ qnw, const float* __restrict__ qnb,
    const float* __restrict__ knw, const float* __restrict__ knb)
{
    __shared__ __align__(16) __nv_bfloat16 sA[2][128 * STR];
    __shared__ __align__(16) __nv_bfloat16 sB[2][128 * STR];

    const int tid = threadIdx.x;
    const int lane = tid & 31, wid = tid >> 5;
    const int wm = wid & 3, wn = wid >> 2;
    const int g = lane >> 2, t4 = lane & 3;
    const int row0 = blockIdx.y * 128;
    const int col0 = blockIdx.x * 128;

    float acc[2][8][4];
    #pragma unroll
    for (int i = 0; i < 2; i++)
        #pragma unroll
        for (int j = 0; j < 8; j++)
            #pragma unroll
            for (int c = 0; c < 4; c++) acc[i][j][c] = 0.f;

    for (int k0 = 0; k0 < CDIM; k0 += 32) {
        #pragma unroll
        for (int it = 0; it < 2; it++) {
            int q = it * 256 + tid;
            int r = q >> 2, c = (q & 3) * 8;
            *(float4*)&sA[0][r * STR + c] = *(const float4*)&g_xh[(size_t)(row0 + r) * CDIM + k0 + c];
            *(float4*)&sA[1][r * STR + c] = *(const float4*)&g_xl[(size_t)(row0 + r) * CDIM + k0 + c];
            *(float4*)&sB[0][r * STR + c] = *(const float4*)&g_wqh[(size_t)(col0 + r) * CDIM + k0 + c];
            *(float4*)&sB[1][r * STR + c] = *(const float4*)&g_wql[(size_t)(col0 + r) * CDIM + k0 + c];
        }
        __syncthreads();

        #pragma unroll
        for (int ks = 0; ks < 2; ks++) {
            unsigned ah[2][4], al[2][4];
            #pragma unroll
            for (int mf = 0; mf < 2; mf++) {
                int base = (wm * 32 + mf * 16 + g) * STR + ks * 16 + t4 * 2;
                ah[mf][0] = *(const unsigned*)&sA[0][base];
                ah[mf][1] = *(const unsigned*)&sA[0][base + 8 * STR];
                ah[mf][2] = *(const unsigned*)&sA[0][base + 8];
                ah[mf][3] = *(const unsigned*)&sA[0][base + 8 * STR + 8];
                al[mf][0] = *(const unsigned*)&sA[1][base];
                al[mf][1] = *(const unsigned*)&sA[1][base + 8 * STR];
                al[mf][2] = *(const unsigned*)&sA[1][base + 8];
                al[mf][3] = *(const unsigned*)&sA[1][base + 8 * STR + 8];
            }
            #pragma unroll
            for (int nf = 0; nf < 8; nf++) {
                int base = (wn * 64 + nf * 8 + g) * STR + ks * 16 + t4 * 2;
                unsigned bh[2] = {*(const unsigned*)&sB[0][base], *(const unsigned*)&sB[0][base + 8]};
                unsigned bl[2] = {*(const unsigned*)&sB[1][base], *(const unsigned*)&sB[1][base + 8]};
                #pragma unroll
                for (int mf = 0; mf < 2; mf++) {
                    mma16816(acc[mf][nf], ah[mf], bh);
                    mma16816(acc[mf][nf], al[mf], bh);
                    mma16816(acc[mf][nf], ah[mf], bl);
                }
            }
        }
        __syncthreads();
    }

    // bias
    const int wcol0 = col0 + wn * 64;
    #pragma unroll
    for (int nf = 0; nf < 8; nf++) {
        int c = wcol0 + nf * 8 + t4 * 2;
        float b0 = bias[c], b1 = bias[c + 1];
        #pragma unroll
        for (int mf = 0; mf < 2; mf++) {
            acc[mf][nf][0] += b0; acc[mf][nf][1] += b1;
            acc[mf][nf][2] += b0; acc[mf][nf][3] += b1;
        }
    }

    const int part = col0 >> 10;            // block fully within one of q/k/v
    const int h = (wcol0 & 1023) >> 6;      // warp tile = one head (64 cols)
    __nv_bfloat16* dh = (part == 0) ? g_qh : (part == 1) ? g_kh : g_vh;
    __nv_bfloat16* dl = (part == 0) ? g_ql : (part == 1) ? g_kl : g_vl;
    const float sc = (part == 0) ? 0.125f : 1.0f;   // D^-0.5 folded into q

    #pragma unroll
    for (int mf = 0; mf < 2; mf++) {
        #pragma unroll
        for (int rs = 0; rs < 2; rs++) {
            float v[16];
            #pragma unroll
            for (int nf = 0; nf < 8; nf++) {
                v[2 * nf]     = acc[mf][nf][rs * 2];
                v[2 * nf + 1] = acc[mf][nf][rs * 2 + 1];
            }
            if (part < 2) {
                const float* nw = (part == 0) ? qnw : knw;
                const float* nb = (part == 0) ? qnb : knb;
                float s = 0.f;
                #pragma unroll
                for (int j = 0; j < 16; j++) s += v[j];
                s += __shfl_xor_sync(0xffffffffu, s, 1, 4);
                s += __shfl_xor_sync(0xffffffffu, s, 2, 4);
                float mean = s * (1.0f / 64.0f);
                float sq = 0.f;
                #pragma unroll
                for (int j = 0; j < 16; j++) { float d = v[j] - mean; sq += d * d; }
                sq += __shfl_xor_sync(0xffffffffu, sq, 1, 4);
                sq += __shfl_xor_sync(0xffffffffu, sq, 2, 4);
                float inv = rsqrtf(sq * (1.0f / 64.0f) + 1e-5f);
                #pragma unroll
                for (int j = 0; j < 16; j++) {
                    int dcol = (j >> 1) * 8 + t4 * 2 + (j & 1);
                    v[j] = ((v[j] - mean) * inv * nw[dcol] + nb[dcol]) * sc;
                }
            }
            int m = row0 + wm * 32 + mf * 16 + g + rs * 8;
            int bb = m >> 12, t = m & 4095;
            size_t base = ((size_t)(bb * HEADS + h) * NTOK + t) * HDIM;
            #pragma unroll
            for (int nf = 0; nf < 8; nf++) {
                int d = nf * 8 + t4 * 2;
                float v0 = v[2 * nf], v1 = v[2 * nf + 1];
                __nv_bfloat16 h0 = __float2bfloat16(v0);
                __nv_bfloat16 h1 = __float2bfloat16(v1);
                __nv_bfloat16 l0 = __float2bfloat16(v0 - __bfloat162float(h0));
                __nv_bfloat16 l1 = __float2bfloat16(v1 - __bfloat162float(h1));
                *(unsigned*)&dh[base + d] = pack2(h0, h1);
                *(unsigned*)&dl[base + d] = pack2(l0, l1);
            }
        }
    }
}

// ---------------------------------------------------------------------------
// Flash attention, bf16x3 mma. Block = 128 queries (8 warps x 16 rows),
// key tile 64. Q frags live in regs; P frags built by register repacking.
// smem rows hold HDIM=64 elems -> stride STRF=72 (conflict-free K frags).
// ---------------------------------------------------------------------------
__global__ __launch_bounds__(256) void flash_mma_kernel()
{
    __shared__ __align__(16) __nv_bfloat16 sK[2][64 * STRF];
    __shared__ __align__(16) __nv_bfloat16 sV[2][64 * STRF];

    const int tid = threadIdx.x;
    const int lane = tid & 31, wid = tid >> 5;
    const int g = lane >> 2, t4 = lane & 3;
    const int qb = blockIdx.x, bh = blockIdx.y;

    const size_t hbase = (size_t)bh * NTOK * HDIM;
    const int qrow = qb * 128 + wid * 16;

    // Q fragments (hi+lo) resident in registers
    unsigned qh[4][4], ql[4][4];
    {
        const __nv_bfloat16* Ph = g_qh + hbase + (size_t)qrow * HDIM;
        const __nv_bfloat16* Pl = g_ql + hbase + (size_t)qrow * HDIM;
        #pragma unroll
        for (int ks = 0; ks < 4; ks++) {
            int c = ks * 16 + t4 * 2;
            qh[ks][0] = *(const unsigned*)&Ph[g * HDIM + c];
            qh[ks][1] = *(const unsigned*)&Ph[(g + 8) * HDIM + c];
            qh[ks][2] = *(const unsigned*)&Ph[g * HDIM + c + 8];
            qh[ks][3] = *(const unsigned*)&Ph[(g + 8) * HDIM + c + 8];
            ql[ks][0] = *(const unsigned*)&Pl[g * HDIM + c];
            ql[ks][1] = *(const unsigned*)&Pl[(g + 8) * HDIM + c];
            ql[ks][2] = *(const unsigned*)&Pl[g * HDIM + c + 8];
            ql[ks][3] = *(const unsigned*)&Pl[(g + 8) * HDIM + c + 8];
        }
    }

    float o[8][4];
    #pragma unroll
    for (int i = 0; i < 8; i++)
        #pragma unroll
        for (int c = 0; c < 4; c++) o[i][c] = 0.f;
    float mrow[2] = {-1e30f, -1e30f};
    float lrow[2] = {0.f, 0.f};

    for (int kt = 0; kt < NTOK / 64; kt++) {
        __syncthreads();
        #pragma unroll
        for (int it = 0; it < 2; it++) {
            int q = it * 256 + tid;
            int r = q >> 3, c = (q & 7) * 8;
            size_t gsrc = hbase + (size_t)(kt * 64 + r) * HDIM + c;
            *(float4*)&sK[0][r * STRF + c] = *(const float4*)&g_kh[gsrc];
            *(float4*)&sK[1][r * STRF + c] = *(const float4*)&g_kl[gsrc];
            *(float4*)&sV[0][r * STRF + c] = *(const float4*)&g_vh[gsrc];
            *(float4*)&sV[1][r * STRF + c] = *(const float4*)&g_vl[gsrc];
        }
        __syncthreads();

        // S = Q K^T (x3 split)
        float s[8][4];
        #pragma unroll
        for (int i = 0; i < 8; i++)
            #pragma unroll
            for (int c = 0; c < 4; c++) s[i][c] = 0.f;
        #pragma unroll
        for (int ks = 0; ks < 4; ks++) {
            #pragma unroll
            for (int nf = 0; nf < 8; nf++) {
                int base = (nf * 8 + g) * STRF + ks * 16 + t4 * 2;
                unsigned kbh[2] = {*(const unsigned*)&sK[0][base], *(const unsigned*)&sK[0][base + 8]};
                unsigned kbl[2] = {*(const unsigned*)&sK[1][base], *(const unsigned*)&sK[1][base + 8]};
                mma16816(s[nf], qh[ks], kbh);
                mma16816(s[nf], ql[ks], kbh);
                mma16816(s[nf], qh[ks], kbl);
            }
        }

        // online softmax (row groups = 4 lanes sharing g)
        #pragma unroll
        for (int rs = 0; rs < 2; rs++) {
            float mx = -1e30f;
            #pragma unroll
            for (int nf = 0; nf < 8; nf++)
                mx = fmaxf(mx, fmaxf(s[nf][rs * 2], s[nf][rs * 2 + 1]));
            mx = fmaxf(mx, __shfl_xor_sync(0xffffffffu, mx, 1, 4));
            mx = fmaxf(mx, __shfl_xor_sync(0xffffffffu, mx, 2, 4));
            float mnew = fmaxf(mrow[rs], mx);
            float alpha = __expf(mrow[rs] - mnew);
            mrow[rs] = mnew;
            float sum = 0.f;
            #pragma unroll
            for (int nf = 0; nf < 8; nf++) {
                float p0 = __expf(s[nf][rs * 2] - mnew);
                float p1 = __expf(s[nf][rs * 2 + 1] - mnew);
                s[nf][rs * 2] = p0; s[nf][rs * 2 + 1] = p1;
                sum += p0 + p1;
            }
            sum += __shfl_xor_sync(0xffffffffu, sum, 1, 4);
            sum += __shfl_xor_sync(0xffffffffu, sum, 2, 4);
            lrow[rs] = lrow[rs] * alpha + sum;
            #pragma unroll
            for (int nfd = 0; nfd < 8; nfd++) {
                o[nfd][rs * 2] *= alpha;
                o[nfd][rs * 2 + 1] *= alpha;
            }
        }

        // O += P V (x3 split); P frags repacked from S accumulators
        #pragma unroll
        for (int ks = 0; ks < 4; ks++) {
            unsigned pah[4], pal[4];
            {
                float p0 = s[2 * ks][0], p1 = s[2 * ks][1];
                float p2 = s[2 * ks][2], p3 = s[2 * ks][3];
                float p4 = s[2 * ks + 1][0], p5 = s[2 * ks + 1][1];
                float p6 = s[2 * ks + 1][2], p7 = s[2 * ks + 1][3];
                __nv_bfloat16 h0 = __float2bfloat16(p0), h1 = __float2bfloat16(p1);
                __nv_bfloat16 h2 = __float2bfloat16(p2), h3 = __float2bfloat16(p3);
                __nv_bfloat16 h4 = __float2bfloat16(p4), h5 = __float2bfloat16(p5);
                __nv_bfloat16 h6 = __float2bfloat16(p6), h7 = __float2bfloat16(p7);
                pah[0] = pack2(h0, h1); pah[1] = pack2(h2, h3);
                pah[2] = pack2(h4, h5); pah[3] = pack2(h6, h7);
                pal[0] = pack2(__float2bfloat16(p0 - __bfloat162float(h0)),
                               __float2bfloat16(p1 - __bfloat162float(h1)));
                pal[1] = pack2(__float2bfloat16(p2 - __bfloat162float(h2)),
                               __float2bfloat16(p3 - __bfloat162float(h3)));
                pal[2] = pack2(__float2bfloat16(p4 - __bfloat162float(h4)),
                               __float2bfloat16(p5 - __bfloat162float(h5)));
                pal[3] = pack2(__float2bfloat16(p6 - __bfloat162float(h6)),
                               __float2bfloat16(p7 - __bfloat162float(h7)));
            }
            #pragma unroll
            for (int nfd = 0; nfd < 8; nfd++) {
                int n = nfd * 8 + g;
                int k0 = ks * 16 + t4 * 2;
                unsigned vbh[2], vbl[2];
                vbh[0] = pack2(sV[0][k0 * STRF + n],       sV[0][(k0 + 1) * STRF + n]);
                vbh[1] = pack2(sV[0][(k0 + 8) * STRF + n], sV[0][(k0 + 9) * STRF + n]);
                vbl[0] = pack2(sV[1][k0 * STRF + n],       sV[1][(k0 + 1) * STRF + n]);
                vbl[1] = pack2(sV[1][(k0 + 8) * STRF + n], sV[1][(k0 + 9) * STRF + n]);
                mma16816(o[nfd], pah, vbh);
                mma16816(o[nfd], pal, vbh);
                mma16816(o[nfd], pah, vbl);
            }
        }
    }

    // epilogue: normalize, split, write O in [B,N,C] (hi/lo)
    const int bb = bh >> 4, hh = bh & 15;
    #pragma unroll
    for (int rs = 0; rs < 2; rs++) {
        float inv = 1.0f / lrow[rs];
        int t = qrow + g + rs * 8;
        size_t base = ((size_t)(bb * NTOK + t)) * CDIM + hh * HDIM;
        #pragma unroll
        for (int nfd = 0; nfd < 8; nfd++) {
            int d = nfd * 8 + t4 * 2;
            float v0 = o[nfd][rs * 2] * inv;
            float v1 = o[nfd][rs * 2 + 1] * inv;
            __nv_bfloat16 h0 = __float2bfloat16(v0);
            __nv_bfloat16 h1 = __float2bfloat16(v1);
            __nv_bfloat16 l0 = __float2bfloat16(v0 - __bfloat162float(h0));
            __nv_bfloat16 l1 = __float2bfloat16(v1 - __bfloat162float(h1));
            *(unsigned*)&g_oh[base + d] = pack2(h0, h1);
            *(unsigned*)&g_ol[base + d] = pack2(l0, l1);
        }
    }
}

// ---------------------------------------------------------------------------
// Output projection GEMM (bf16x3 split) + bias -> fp32 d_out
// ---------------------------------------------------------------------------
__global__ __launch_bounds__(256) void proj_mma_kernel(
    const float* __restrict__ bias, float* __restrict__ out)
{
    __shared__ __align__(16) __nv_bfloat16 sA[2][128 * STR];
    __shared__ __align__(16) __nv_bfloat16 sB[2][128 * STR];

    const int tid = threadIdx.x;
    const int lane = tid & 31, wid = tid >> 5;
    const int wm = wid & 3, wn = wid >> 2;
    const int g = lane >> 2, t4 = lane & 3;
    const int row0 = blockIdx.y * 128;
    const int col0 = blockIdx.x * 128;

    float acc[2][8][4];
    #pragma unroll
    for (int i = 0; i < 2; i++)
        #pragma unroll
        for (int j = 0; j < 8; j++)
            #pragma unroll
            for (int c = 0; c < 4; c++) acc[i][j][c] = 0.f;

    for (int k0 = 0; k0 < CDIM; k0 += 32) {
        #pragma unroll
        for (int it = 0; it < 2; it++) {
            int q = it * 256 + tid;
            int r = q >> 2, c = (q & 3) * 8;
            *(float4*)&sA[0][r * STR + c] = *(const float4*)&g_oh[(size_t)(row0 + r) * CDIM + k0 + c];
            *(float4*)&sA[1][r * STR + c] = *(const float4*)&g_ol[(size_t)(row0 + r) * CDIM + k0 + c];
            *(float4*)&sB[0][r * STR + c] = *(const float4*)&g_wph[(size_t)(col0 + r) * CDIM + k0 + c];
            *(float4*)&sB[1][r * STR + c] = *(const float4*)&g_wpl[(size_t)(col0 + r) * CDIM + k0 + c];
        }
        __syncthreads();

        #pragma unroll
        for (int ks = 0; ks < 2; ks++) {
            unsigned ah[2][4], al[2][4];
            #pragma unroll
            for (int mf = 0; mf < 2; mf++) {
                int base = (wm * 32 + mf * 16 + g) * STR + ks * 16 + t4 * 2;
                ah[mf][0] = *(const unsigned*)&sA[0][base];
                ah[mf][1] = *(const unsigned*)&sA[0][base + 8 * STR];
                ah[mf][2] = *(const unsigned*)&sA[0][base + 8];
                ah[mf][3] = *(const unsigned*)&sA[0][base + 8 * STR + 8];
                al[mf][0] = *(const unsigned*)&sA[1][base];
                al[mf][1] = *(const unsigned*)&sA[1][base + 8 * STR];
                al[mf][2] = *(const unsigned*)&sA[1][base + 8];
                al[mf][3] = *(const unsigned*)&sA[1][base + 8 * STR + 8];
            }
            #pragma unroll
            for (int nf = 0; nf < 8; nf++) {
                int base = (wn * 64 + nf * 8 + g) * STR + ks * 16 + t4 * 2;
                unsigned bh[2] = {*(const unsigned*)&sB[0][base], *(const unsigned*)&sB[0][base + 8]};
                unsigned bl[2] = {*(const unsigned*)&sB[1][base], *(const unsigned*)&sB[1][base + 8]};
                #pragma unroll
                for (int mf = 0; mf < 2; mf++) {
                    mma16816(acc[mf][nf], ah[mf], bh);
                    mma16816(acc[mf][nf], al[mf], bh);
                    mma16816(acc[mf][nf], ah[mf], bl);
                }
            }
        }
        __syncthreads();
    }

    const int wcol0 = col0 + wn * 64;
    #pragma unroll
    for (int mf = 0; mf < 2; mf++) {
        #pragma unroll
        for (int rs = 0; rs < 2; rs++) {
            int m = row0 + wm * 32 + mf * 16 + g + rs * 8;
            #pragma unroll
            for (int nf = 0; nf < 8; nf++) {
                int c = wcol0 + nf * 8 + t4 * 2;
                float2 r;
                r.x = acc[mf][nf][rs * 2]     + bias[c];
                r.y = acc[mf][nf][rs * 2 + 1] + bias[c + 1];
                *(float2*)&out[(size_t)m * CDIM + c] = r;
            }
        }
    }
}

// ---------------------------------------------------------------------------
extern "C" void kernel_launch(void* const* d_in, const int* in_sizes, int n_in,
                              void* d_out, int out_size)
{
    const float* x      = (const float*)d_in[0];
    const float* qkv_w  = (const float*)d_in[1];
    const float* qkv_b  = (const float*)d_in[2];
    const float* qnw    = (const float*)d_in[3];
    const float* qnb    = (const float*)d_in[4];
    const float* knw    = (const float*)d_in[5];
    const float* knb    = (const float*)d_in[6];
    const float* proj_w = (const float*)d_in[7];
    const float* pb     = (const float*)d_in[8];
    float* out = (float*)d_out;

    convert_kernel<<<2048, 256>>>(x, 0, MROWS * CDIM);
    convert_kernel<<<1024, 256>>>(qkv_w, 1, QKVN * CDIM);
    convert_kernel<<<512, 256>>>(proj_w, 2, CDIM * CDIM);

    qkv_mma_kernel<<<dim3(QKVN / 128, MROWS / 128), 256>>>(qkv_b, qnw, qnb, knw, knb);
    flash_mma_kernel<<<dim3(NTOK / 128, BATCH * HEADS), 256>>>();
    proj_mma_kernel<<<dim3(CDIM / 128, MROWS / 128), 256>>>(pb, out);
}

// round 10
// speedup vs baseline: 3.1570x; 1.1598x over previous
#include <cuda_runtime.h>
#include <cuda_bf16.h>

#define BATCH 2
#define NTOK 4096
#define CDIM 1024
#define HEADS 16
#define HDIM 64
#define MROWS (BATCH * NTOK)          // 8192
#define QKVN (3 * CDIM)               // 3072
#define PHE (BATCH * HEADS * NTOK * HDIM)  // 8,388,608
#define STR 40                        // GEMM smem row stride (BK=32 + pad)
#define STRF 72                       // flash smem row stride (64 + pad)

// ---- static scratch ----
__device__ __align__(16) __nv_bfloat16 g_xh[MROWS * CDIM], g_xl[MROWS * CDIM];
__device__ __align__(16) __nv_bfloat16 g_wqh[QKVN * CDIM], g_wql[QKVN * CDIM];
__device__ __align__(16) __nv_bfloat16 g_wph[CDIM * CDIM], g_wpl[CDIM * CDIM];
__device__ __align__(16) __nv_bfloat16 g_qh[PHE], g_ql[PHE];
__device__ __align__(16) __nv_bfloat16 g_kh[PHE], g_kl[PHE];
__device__ __align__(16) __nv_bfloat16 g_vth[PHE], g_vtl[PHE];   // V transposed [B,H,D,N]
__device__ __align__(16) __nv_bfloat16 g_oh[MROWS * CDIM], g_ol[MROWS * CDIM];

__device__ __forceinline__ unsigned pack2(__nv_bfloat16 a, __nv_bfloat16 b) {
    __nv_bfloat162 t = __halves2bfloat162(a, b);
    return *reinterpret_cast<unsigned*>(&t);
}

__device__ __forceinline__ void mma16816(float c[4], const unsigned a[4], const unsigned b[2]) {
    asm volatile(
        "mma.sync.aligned.m16n8k16.row.col.f32.bf16.bf16.f32 "
        "{%0,%1,%2,%3}, {%4,%5,%6,%7}, {%8,%9}, {%0,%1,%2,%3};\n"
        : "+f"(c[0]), "+f"(c[1]), "+f"(c[2]), "+f"(c[3])
        : "r"(a[0]), "r"(a[1]), "r"(a[2]), "r"(a[3]), "r"(b[0]), "r"(b[1]));
}

__device__ __forceinline__ void cpa16(__nv_bfloat16* smem, const __nv_bfloat16* gmem) {
    unsigned s = (unsigned)__cvta_generic_to_shared(smem);
    asm volatile("cp.async.cg.shared.global [%0], [%1], 16;\n" :: "r"(s), "l"(gmem));
}
#define CPA_COMMIT() asm volatile("cp.async.commit_group;\n" ::: "memory")
#define CPA_WAIT1()  asm volatile("cp.async.wait_group 1;\n" ::: "memory")

// ---------------------------------------------------------------------------
__global__ void convert_kernel(const float* __restrict__ src, int which, int n) {
    __nv_bfloat16 *h, *l;
    if (which == 0)      { h = g_xh;  l = g_xl;  }
    else if (which == 1) { h = g_wqh; l = g_wql; }
    else                 { h = g_wph; l = g_wpl; }
    for (int i = blockIdx.x * blockDim.x + threadIdx.x; i < n;
         i += gridDim.x * blockDim.x) {
        float x = src[i];
        __nv_bfloat16 hi = __float2bfloat16(x);
        h[i] = hi;
        l[i] = __float2bfloat16(x - __bfloat162float(hi));
    }
}

// ---------------------------------------------------------------------------
// QKV GEMM (bf16x3, mma.sync, cp.async 2-stage) + bias + fused per-head LN.
// Block 128x128, BK=32, 8 warps 4(m)x2(n). Dynamic smem: 2 stages x 4 arrays.
// Stage layout (bf16 elems): [Ah 5120][Al 5120][Bh 5120][Bl 5120] = 20480.
// ---------------------------------------------------------------------------
#define GSTG (128 * STR)           // 5120
#define GSTAGE (4 * GSTG)          // 20480 elems = 40960 B

__global__ __launch_bounds__(256, 2) void qkv_mma_kernel(
    const float* __restrict__ bias,
    const float* __restrict__ qnw, const float* __restrict__ qnb,
    const float* __restrict__ knw, const float* __restrict__ knb)
{
    extern __shared__ __align__(16) __nv_bfloat16 dyn[];

    const int tid = threadIdx.x;
    const int lane = tid & 31, wid = tid >> 5;
    const int wm = wid & 3, wn = wid >> 2;
    const int g = lane >> 2, t4 = lane & 3;
    const int row0 = blockIdx.y * 128;
    const int col0 = blockIdx.x * 128;

    const int lr0 = tid >> 2, lc0 = (tid & 3) * 8;
    const int lr1 = (256 + tid) >> 2, lc1 = lc0;

    float acc[2][8][4];
    #pragma unroll
    for (int i = 0; i < 2; i++)
        #pragma unroll
        for (int j = 0; j < 8; j++)
            #pragma unroll
            for (int c = 0; c < 4; c++) acc[i][j][c] = 0.f;

    // prologue: stage 0
    {
        __nv_bfloat16* s = dyn;
        cpa16(&s[0 * GSTG + lr0 * STR + lc0], &g_xh [(size_t)(row0 + lr0) * CDIM + lc0]);
        cpa16(&s[0 * GSTG + lr1 * STR + lc1], &g_xh [(size_t)(row0 + lr1) * CDIM + lc1]);
        cpa16(&s[1 * GSTG + lr0 * STR + lc0], &g_xl [(size_t)(row0 + lr0) * CDIM + lc0]);
        cpa16(&s[1 * GSTG + lr1 * STR + lc1], &g_xl [(size_t)(row0 + lr1) * CDIM + lc1]);
        cpa16(&s[2 * GSTG + lr0 * STR + lc0], &g_wqh[(size_t)(col0 + lr0) * CDIM + lc0]);
        cpa16(&s[2 * GSTG + lr1 * STR + lc1], &g_wqh[(size_t)(col0 + lr1) * CDIM + lc1]);
        cpa16(&s[3 * GSTG + lr0 * STR + lc0], &g_wql[(size_t)(col0 + lr0) * CDIM + lc0]);
        cpa16(&s[3 * GSTG + lr1 * STR + lc1], &g_wql[(size_t)(col0 + lr1) * CDIM + lc1]);
        CPA_COMMIT();
    }

    for (int kt = 0; kt < CDIM / 32; kt++) {
        __syncthreads();   // all warps done reading buffer (kt+1)&1 (iter kt-1)
        if (kt + 1 < CDIM / 32) {
            __nv_bfloat16* s = dyn + ((kt + 1) & 1) * GSTAGE;
            int k0 = (kt + 1) * 32;
            cpa16(&s[0 * GSTG + lr0 * STR + lc0], &g_xh [(size_t)(row0 + lr0) * CDIM + k0 + lc0]);
            cpa16(&s[0 * GSTG + lr1 * STR + lc1], &g_xh [(size_t)(row0 + lr1) * CDIM + k0 + lc1]);
            cpa16(&s[1 * GSTG + lr0 * STR + lc0], &g_xl [(size_t)(row0 + lr0) * CDIM + k0 + lc0]);
            cpa16(&s[1 * GSTG + lr1 * STR + lc1], &g_xl [(size_t)(row0 + lr1) * CDIM + k0 + lc1]);
            cpa16(&s[2 * GSTG + lr0 * STR + lc0], &g_wqh[(size_t)(col0 + lr0) * CDIM + k0 + lc0]);
            cpa16(&s[2 * GSTG + lr1 * STR + lc1], &g_wqh[(size_t)(col0 + lr1) * CDIM + k0 + lc1]);
            cpa16(&s[3 * GSTG + lr0 * STR + lc0], &g_wql[(size_t)(col0 + lr0) * CDIM + k0 + lc0]);
            cpa16(&s[3 * GSTG + lr1 * STR + lc1], &g_wql[(size_t)(col0 + lr1) * CDIM + k0 + lc1]);
        }
        CPA_COMMIT();
        CPA_WAIT1();
        __syncthreads();

        const __nv_bfloat16* pAh = dyn + (kt & 1) * GSTAGE;
        const __nv_bfloat16* pAl = pAh + GSTG;
        const __nv_bfloat16* pBh = pAl + GSTG;
        const __nv_bfloat16* pBl = pBh + GSTG;

        #pragma unroll
        for (int ks = 0; ks < 2; ks++) {
            unsigned ah[2][4], al[2][4];
            #pragma unroll
            for (int mf = 0; mf < 2; mf++) {
                int base = (wm * 32 + mf * 16 + g) * STR + ks * 16 + t4 * 2;
                ah[mf][0] = *(const unsigned*)&pAh[base];
                ah[mf][1] = *(const unsigned*)&pAh[base + 8 * STR];
                ah[mf][2] = *(const unsigned*)&pAh[base + 8];
                ah[mf][3] = *(const unsigned*)&pAh[base + 8 * STR + 8];
                al[mf][0] = *(const unsigned*)&pAl[base];
                al[mf][1] = *(const unsigned*)&pAl[base + 8 * STR];
                al[mf][2] = *(const unsigned*)&pAl[base + 8];
                al[mf][3] = *(const unsigned*)&pAl[base + 8 * STR + 8];
            }
            #pragma unroll
            for (int nf = 0; nf < 8; nf++) {
                int base = (wn * 64 + nf * 8 + g) * STR + ks * 16 + t4 * 2;
                unsigned bh[2] = {*(const unsigned*)&pBh[base], *(const unsigned*)&pBh[base + 8]};
                unsigned bl[2] = {*(const unsigned*)&pBl[base], *(const unsigned*)&pBl[base + 8]};
                #pragma unroll
                for (int mf = 0; mf < 2; mf++) {
                    mma16816(acc[mf][nf], ah[mf], bh);
                    mma16816(acc[mf][nf], al[mf], bh);
                    mma16816(acc[mf][nf], ah[mf], bl);
                }
            }
        }
    }

    // bias
    const int wcol0 = col0 + wn * 64;
    #pragma unroll
    for (int nf = 0; nf < 8; nf++) {
        int c = wcol0 + nf * 8 + t4 * 2;
        float b0 = bias[c], b1 = bias[c + 1];
        #pragma unroll
        for (int mf = 0; mf < 2; mf++) {
            acc[mf][nf][0] += b0; acc[mf][nf][1] += b1;
            acc[mf][nf][2] += b0; acc[mf][nf][3] += b1;
        }
    }

    const int part = col0 >> 10;
    const int h = (wcol0 & 1023) >> 6;
    const float sc = (part == 0) ? 0.125f : 1.0f;

    #pragma unroll
    for (int mf = 0; mf < 2; mf++) {
        #pragma unroll
        for (int rs = 0; rs < 2; rs++) {
            float v[16];
            #pragma unroll
            for (int nf = 0; nf < 8; nf++) {
                v[2 * nf]     = acc[mf][nf][rs * 2];
                v[2 * nf + 1] = acc[mf][nf][rs * 2 + 1];
            }
            if (part < 2) {
                const float* nw = (part == 0) ? qnw : knw;
                const float* nb = (part == 0) ? qnb : knb;
                float s = 0.f;
                #pragma unroll
                for (int j = 0; j < 16; j++) s += v[j];
                s += __shfl_xor_sync(0xffffffffu, s, 1, 4);
                s += __shfl_xor_sync(0xffffffffu, s, 2, 4);
                float mean = s * (1.0f / 64.0f);
                float sq = 0.f;
                #pragma unroll
                for (int j = 0; j < 16; j++) { float d = v[j] - mean; sq += d * d; }
                sq += __shfl_xor_sync(0xffffffffu, sq, 1, 4);
                sq += __shfl_xor_sync(0xffffffffu, sq, 2, 4);
                float inv = rsqrtf(sq * (1.0f / 64.0f) + 1e-5f);
                #pragma unroll
                for (int j = 0; j < 16; j++) {
                    int dcol = (j >> 1) * 8 + t4 * 2 + (j & 1);
                    v[j] = ((v[j] - mean) * inv * nw[dcol] + nb[dcol]) * sc;
                }
            }
            int m = row0 + wm * 32 + mf * 16 + g + rs * 8;
            int bb = m >> 12, t = m & 4095;
            if (part < 2) {
                __nv_bfloat16* dh = (part == 0) ? g_qh : g_kh;
                __nv_bfloat16* dl = (part == 0) ? g_ql : g_kl;
                size_t base = ((size_t)(bb * HEADS + h) * NTOK + t) * HDIM;
                #pragma unroll
                for (int nf = 0; nf < 8; nf++) {
                    int d = nf * 8 + t4 * 2;
                    float v0 = v[2 * nf], v1 = v[2 * nf + 1];
                    __nv_bfloat16 h0 = __float2bfloat16(v0);
                    __nv_bfloat16 h1 = __float2bfloat16(v1);
                    *(unsigned*)&dh[base + d] = pack2(h0, h1);
                    *(unsigned*)&dl[base + d] =
                        pack2(__float2bfloat16(v0 - __bfloat162float(h0)),
                              __float2bfloat16(v1 - __bfloat162float(h1)));
                }
            } else {
                // V: write transposed [B,H,D,N] (scalar 2B stores, 8-lane coalesced)
                size_t vbase = (size_t)(bb * HEADS + h) * HDIM * NTOK + t;
                #pragma unroll
                for (int nf = 0; nf < 8; nf++) {
                    int d = nf * 8 + t4 * 2;
                    float v0 = v[2 * nf], v1 = v[2 * nf + 1];
                    __nv_bfloat16 h0 = __float2bfloat16(v0);
                    __nv_bfloat16 h1 = __float2bfloat16(v1);
                    g_vth[vbase + (size_t)d * NTOK]       = h0;
                    g_vth[vbase + (size_t)(d + 1) * NTOK] = h1;
                    g_vtl[vbase + (size_t)d * NTOK]       = __float2bfloat16(v0 - __bfloat162float(h0));
                    g_vtl[vbase + (size_t)(d + 1) * NTOK] = __float2bfloat16(v1 - __bfloat162float(h1));
                }
            }
        }
    }
}

// ---------------------------------------------------------------------------
// Flash attention (bf16x3, cp.async 2-stage). Block = 128 q (8 warps x 16).
// K natural [key][d]; V transposed [d][key] -> b32 B-frag loads.
// Stage layout (bf16): [Kh 4608][Kl 4608][Vth 4608][Vtl 4608] = 18432.
// ---------------------------------------------------------------------------
#define FSTG (64 * STRF)            // 4608
#define FSTAGE (4 * FSTG)           // 18432 elems = 36864 B
#define NKT (NTOK / 64)

__global__ __launch_bounds__(256) void flash_mma_kernel()
{
    extern __shared__ __align__(16) __nv_bfloat16 fdyn[];

    const int tid = threadIdx.x;
    const int lane = tid & 31, wid = tid >> 5;
    const int g = lane >> 2, t4 = lane & 3;
    const int qb = blockIdx.x, bh = blockIdx.y;

    const size_t hbase = (size_t)bh * NTOK * HDIM;   // for q/k [bh][t][d]
    const size_t vbase = (size_t)bh * HDIM * NTOK;   // for vT  [bh][d][t]
    const int qrow = qb * 128 + wid * 16;

    const int fr0 = tid >> 3, fc0 = (tid & 7) * 8;
    const int fr1 = (256 + tid) >> 3, fc1 = fc0;

    // Q fragments resident
    unsigned qh[4][4], ql[4][4];
    {
        const __nv_bfloat16* Ph = g_qh + hbase + (size_t)qrow * HDIM;
        const __nv_bfloat16* Pl = g_ql + hbase + (size_t)qrow * HDIM;
        #pragma unroll
        for (int ks = 0; ks < 4; ks++) {
            int c = ks * 16 + t4 * 2;
            qh[ks][0] = *(const unsigned*)&Ph[g * HDIM + c];
            qh[ks][1] = *(const unsigned*)&Ph[(g + 8) * HDIM + c];
            qh[ks][2] = *(const unsigned*)&Ph[g * HDIM + c + 8];
            qh[ks][3] = *(const unsigned*)&Ph[(g + 8) * HDIM + c + 8];
            ql[ks][0] = *(const unsigned*)&Pl[g * HDIM + c];
            ql[ks][1] = *(const unsigned*)&Pl[(g + 8) * HDIM + c];
            ql[ks][2] = *(const unsigned*)&Pl[g * HDIM + c + 8];
            ql[ks][3] = *(const unsigned*)&Pl[(g + 8) * HDIM + c + 8];
        }
    }

    float o[8][4];
    #pragma unroll
    for (int i = 0; i < 8; i++)
        #pragma unroll
        for (int c = 0; c < 4; c++) o[i][c] = 0.f;
    float mrow[2] = {-1e30f, -1e30f};
    float lrow[2] = {0.f, 0.f};

    // prologue: stage 0 (tile 0)
    {
        __nv_bfloat16* s = fdyn;
        cpa16(&s[0 * FSTG + fr0 * STRF + fc0], &g_kh [hbase + (size_t)fr0 * HDIM + fc0]);
        cpa16(&s[0 * FSTG + fr1 * STRF + fc1], &g_kh [hbase + (size_t)fr1 * HDIM + fc1]);
        cpa16(&s[1 * FSTG + fr0 * STRF + fc0], &g_kl [hbase + (size_t)fr0 * HDIM + fc0]);
        cpa16(&s[1 * FSTG + fr1 * STRF + fc1], &g_kl [hbase + (size_t)fr1 * HDIM + fc1]);
        cpa16(&s[2 * FSTG + fr0 * STRF + fc0], &g_vth[vbase + (size_t)fr0 * NTOK + fc0]);
        cpa16(&s[2 * FSTG + fr1 * STRF + fc1], &g_vth[vbase + (size_t)fr1 * NTOK + fc1]);
        cpa16(&s[3 * FSTG + fr0 * STRF + fc0], &g_vtl[vbase + (size_t)fr0 * NTOK + fc0]);
        cpa16(&s[3 * FSTG + fr1 * STRF + fc1], &g_vtl[vbase + (size_t)fr1 * NTOK + fc1]);
        CPA_COMMIT();
    }

    for (int kt = 0; kt < NKT; kt++) {
        __syncthreads();
        if (kt + 1 < NKT) {
            __nv_bfloat16* s = fdyn + ((kt + 1) & 1) * FSTAGE;
            size_t koff = hbase + (size_t)(kt + 1) * 64 * HDIM;
            size_t voff = vbase + (size_t)(kt + 1) * 64;
            cpa16(&s[0 * FSTG + fr0 * STRF + fc0], &g_kh [koff + (size_t)fr0 * HDIM + fc0]);
            cpa16(&s[0 * FSTG + fr1 * STRF + fc1], &g_kh [koff + (size_t)fr1 * HDIM + fc1]);
            cpa16(&s[1 * FSTG + fr0 * STRF + fc0], &g_kl [koff + (size_t)fr0 * HDIM + fc0]);
            cpa16(&s[1 * FSTG + fr1 * STRF + fc1], &g_kl [koff + (size_t)fr1 * HDIM + fc1]);
            cpa16(&s[2 * FSTG + fr0 * STRF + fc0], &g_vth[voff + (size_t)fr0 * NTOK + fc0]);
            cpa16(&s[2 * FSTG + fr1 * STRF + fc1], &g_vth[voff + (size_t)fr1 * NTOK + fc1]);
            cpa16(&s[3 * FSTG + fr0 * STRF + fc0], &g_vtl[voff + (size_t)fr0 * NTOK + fc0]);
            cpa16(&s[3 * FSTG + fr1 * STRF + fc1], &g_vtl[voff + (size_t)fr1 * NTOK + fc1]);
        }
        CPA_COMMIT();
        CPA_WAIT1();
        __syncthreads();

        const __nv_bfloat16* pKh = fdyn + (kt & 1) * FSTAGE;
        const __nv_bfloat16* pKl = pKh + FSTG;
        const __nv_bfloat16* pVh = pKl + FSTG;
        const __nv_bfloat16* pVl = pVh + FSTG;

        // S = Q K^T
        float s[8][4];
        #pragma unroll
        for (int i = 0; i < 8; i++)
            #pragma unroll
            for (int c = 0; c < 4; c++) s[i][c] = 0.f;
        #pragma unroll
        for (int ks = 0; ks < 4; ks++) {
            #pragma unroll
            for (int nf = 0; nf < 8; nf++) {
                int base = (nf * 8 + g) * STRF + ks * 16 + t4 * 2;
                unsigned kbh[2] = {*(const unsigned*)&pKh[base], *(const unsigned*)&pKh[base + 8]};
                unsigned kbl[2] = {*(const unsigned*)&pKl[base], *(const unsigned*)&pKl[base + 8]};
                mma16816(s[nf], qh[ks], kbh);
                mma16816(s[nf], ql[ks], kbh);
                mma16816(s[nf], qh[ks], kbl);
            }
        }

        // online softmax (quad groups share row)
        #pragma unroll
        for (int rs = 0; rs < 2; rs++) {
            float mx = -1e30f;
            #pragma unroll
            for (int nf = 0; nf < 8; nf++)
                mx = fmaxf(mx, fmaxf(s[nf][rs * 2], s[nf][rs * 2 + 1]));
            mx = fmaxf(mx, __shfl_xor_sync(0xffffffffu, mx, 1, 4));
            mx = fmaxf(mx, __shfl_xor_sync(0xffffffffu, mx, 2, 4));
            float mnew = fmaxf(mrow[rs], mx);
            float alpha = __expf(mrow[rs] - mnew);
            mrow[rs] = mnew;
            float sum = 0.f;
            #pragma unroll
            for (int nf = 0; nf < 8; nf++) {
                float p0 = __expf(s[nf][rs * 2] - mnew);
                float p1 = __expf(s[nf][rs * 2 + 1] - mnew);
                s[nf][rs * 2] = p0; s[nf][rs * 2 + 1] = p1;
                sum += p0 + p1;
            }
            sum += __shfl_xor_sync(0xffffffffu, sum, 1, 4);
            sum += __shfl_xor_sync(0xffffffffu, sum, 2, 4);
            lrow[rs] = lrow[rs] * alpha + sum;
            #pragma unroll
            for (int nfd = 0; nfd < 8; nfd++) {
                o[nfd][rs * 2] *= alpha;
                o[nfd][rs * 2 + 1] *= alpha;
            }
        }

        // O += P V  (P repacked from accumulators; V B-frags = b32 loads)
        #pragma unroll
        for (int ks = 0; ks < 4; ks++) {
            unsigned pah[4], pal[4];
            {
                float p0 = s[2 * ks][0], p1 = s[2 * ks][1];
                float p2 = s[2 * ks][2], p3 = s[2 * ks][3];
                float p4 = s[2 * ks + 1][0], p5 = s[2 * ks + 1][1];
                float p6 = s[2 * ks + 1][2], p7 = s[2 * ks + 1][3];
                __nv_bfloat16 h0 = __float2bfloat16(p0), h1 = __float2bfloat16(p1);
                __nv_bfloat16 h2 = __float2bfloat16(p2), h3 = __float2bfloat16(p3);
                __nv_bfloat16 h4 = __float2bfloat16(p4), h5 = __float2bfloat16(p5);
                __nv_bfloat16 h6 = __float2bfloat16(p6), h7 = __float2bfloat16(p7);
                pah[0] = pack2(h0, h1); pah[1] = pack2(h2, h3);
                pah[2] = pack2(h4, h5); pah[3] = pack2(h6, h7);
                pal[0] = pack2(__float2bfloat16(p0 - __bfloat162float(h0)),
                               __float2bfloat16(p1 - __bfloat162float(h1)));
                pal[1] = pack2(__float2bfloat16(p2 - __bfloat162float(h2)),
                               __float2bfloat16(p3 - __bfloat162float(h3)));
                pal[2] = pack2(__float2bfloat16(p4 - __bfloat162float(h4)),
                               __float2bfloat16(p5 - __bfloat162float(h5)));
                pal[3] = pack2(__float2bfloat16(p6 - __bfloat162float(h6)),
                               __float2bfloat16(p7 - __bfloat162float(h7)));
            }
            #pragma unroll
            for (int nfd = 0; nfd < 8; nfd++) {
                int n = nfd * 8 + g;
                int k0 = ks * 16 + t4 * 2;
                unsigned vbh[2] = {*(const unsigned*)&pVh[n * STRF + k0],
                                   *(const unsigned*)&pVh[n * STRF + k0 + 8]};
                unsigned vbl[2] = {*(const unsigned*)&pVl[n * STRF + k0],
                                   *(const unsigned*)&pVl[n * STRF + k0 + 8]};
                mma16816(o[nfd], pah, vbh);
                mma16816(o[nfd], pal, vbh);
                mma16816(o[nfd], pah, vbl);
            }
        }
    }

    // epilogue
    const int bb = bh >> 4, hh = bh & 15;
    #pragma unroll
    for (int rs = 0; rs < 2; rs++) {
        float inv = 1.0f / lrow[rs];
        int t = qrow + g + rs * 8;
        size_t base = ((size_t)(bb * NTOK + t)) * CDIM + hh * HDIM;
        #pragma unroll
        for (int nfd = 0; nfd < 8; nfd++) {
            int d = nfd * 8 + t4 * 2;
            float v0 = o[nfd][rs * 2] * inv;
            float v1 = o[nfd][rs * 2 + 1] * inv;
            __nv_bfloat16 h0 = __float2bfloat16(v0);
            __nv_bfloat16 h1 = __float2bfloat16(v1);
            *(unsigned*)&g_oh[base + d] = pack2(h0, h1);
            *(unsigned*)&g_ol[base + d] =
                pack2(__float2bfloat16(v0 - __bfloat162float(h0)),
                      __float2bfloat16(v1 - __bfloat162float(h1)));
        }
    }
}

// ---------------------------------------------------------------------------
// Output projection GEMM (bf16x3, cp.async 2-stage) + bias -> fp32 d_out
// ---------------------------------------------------------------------------
__global__ __launch_bounds__(256, 2) void proj_mma_kernel(
    const float* __restrict__ bias, float* __restrict__ out)
{
    extern __shared__ __align__(16) __nv_bfloat16 dyn[];

    const int tid = threadIdx.x;
    const int lane = tid & 31, wid = tid >> 5;
    const int wm = wid & 3, wn = wid >> 2;
    const int g = lane >> 2, t4 = lane & 3;
    const int row0 = blockIdx.y * 128;
    const int col0 = blockIdx.x * 128;

    const int lr0 = tid >> 2, lc0 = (tid & 3) * 8;
    const int lr1 = (256 + tid) >> 2, lc1 = lc0;

    float acc[2][8][4];
    #pragma unroll
    for (int i = 0; i < 2; i++)
        #pragma unroll
        for (int j = 0; j < 8; j++)
            #pragma unroll
            for (int c = 0; c < 4; c++) acc[i][j][c] = 0.f;

    {
        __nv_bfloat16* s = dyn;
        cpa16(&s[0 * GSTG + lr0 * STR + lc0], &g_oh [(size_t)(row0 + lr0) * CDIM + lc0]);
        cpa16(&s[0 * GSTG + lr1 * STR + lc1], &g_oh [(size_t)(row0 + lr1) * CDIM + lc1]);
        cpa16(&s[1 * GSTG + lr0 * STR + lc0], &g_ol [(size_t)(row0 + lr0) * CDIM + lc0]);
        cpa16(&s[1 * GSTG + lr1 * STR + lc1], &g_ol [(size_t)(row0 + lr1) * CDIM + lc1]);
        cpa16(&s[2 * GSTG + lr0 * STR + lc0], &g_wph[(size_t)(col0 + lr0) * CDIM + lc0]);
        cpa16(&s[2 * GSTG + lr1 * STR + lc1], &g_wph[(size_t)(col0 + lr1) * CDIM + lc1]);
        cpa16(&s[3 * GSTG + lr0 * STR + lc0], &g_wpl[(size_t)(col0 + lr0) * CDIM + lc0]);
        cpa16(&s[3 * GSTG + lr1 * STR + lc1], &g_wpl[(size_t)(col0 + lr1) * CDIM + lc1]);
        CPA_COMMIT();
    }

    for (int kt = 0; kt < CDIM / 32; kt++) {
        __syncthreads();
        if (kt + 1 < CDIM / 32) {
            __nv_bfloat16* s = dyn + ((kt + 1) & 1) * GSTAGE;
            int k0 = (kt + 1) * 32;
            cpa16(&s[0 * GSTG + lr0 * STR + lc0], &g_oh [(size_t)(row0 + lr0) * CDIM + k0 + lc0]);
            cpa16(&s[0 * GSTG + lr1 * STR + lc1], &g_oh [(size_t)(row0 + lr1) * CDIM + k0 + lc1]);
            cpa16(&s[1 * GSTG + lr0 * STR + lc0], &g_ol [(size_t)(row0 + lr0) * CDIM + k0 + lc0]);
            cpa16(&s[1 * GSTG + lr1 * STR + lc1], &g_ol [(size_t)(row0 + lr1) * CDIM + k0 + lc1]);
            cpa16(&s[2 * GSTG + lr0 * STR + lc0], &g_wph[(size_t)(col0 + lr0) * CDIM + k0 + lc0]);
            cpa16(&s[2 * GSTG + lr1 * STR + lc1], &g_wph[(size_t)(col0 + lr1) * CDIM + k0 + lc1]);
            cpa16(&s[3 * GSTG + lr0 * STR + lc0], &g_wpl[(size_t)(col0 + lr0) * CDIM + k0 + lc0]);
            cpa16(&s[3 * GSTG + lr1 * STR + lc1], &g_wpl[(size_t)(col0 + lr1) * CDIM + k0 + lc1]);
        }
        CPA_COMMIT();
        CPA_WAIT1();
        __syncthreads();

        const __nv_bfloat16* pAh = dyn + (kt & 1) * GSTAGE;
        const __nv_bfloat16* pAl = pAh + GSTG;
        const __nv_bfloat16* pBh = pAl + GSTG;
        const __nv_bfloat16* pBl = pBh + GSTG;

        #pragma unroll
        for (int ks = 0; ks < 2; ks++) {
            unsigned ah[2][4], al[2][4];
            #pragma unroll
            for (int mf = 0; mf < 2; mf++) {
                int base = (wm * 32 + mf * 16 + g) * STR + ks * 16 + t4 * 2;
                ah[mf][0] = *(const unsigned*)&pAh[base];
                ah[mf][1] = *(const unsigned*)&pAh[base + 8 * STR];
                ah[mf][2] = *(const unsigned*)&pAh[base + 8];
                ah[mf][3] = *(const unsigned*)&pAh[base + 8 * STR + 8];
                al[mf][0] = *(const unsigned*)&pAl[base];
                al[mf][1] = *(const unsigned*)&pAl[base + 8 * STR];
                al[mf][2] = *(const unsigned*)&pAl[base + 8];
                al[mf][3] = *(const unsigned*)&pAl[base + 8 * STR + 8];
            }
            #pragma unroll
            for (int nf = 0; nf < 8; nf++) {
                int base = (wn * 64 + nf * 8 + g) * STR + ks * 16 + t4 * 2;
                unsigned bh[2] = {*(const unsigned*)&pBh[base], *(const unsigned*)&pBh[base + 8]};
                unsigned bl[2] = {*(const unsigned*)&pBl[base], *(const unsigned*)&pBl[base + 8]};
                #pragma unroll
                for (int mf = 0; mf < 2; mf++) {
                    mma16816(acc[mf][nf], ah[mf], bh);
                    mma16816(acc[mf][nf], al[mf], bh);
                    mma16816(acc[mf][nf], ah[mf], bl);
                }
            }
        }
    }

    const int wcol0 = col0 + wn * 64;
    #pragma unroll
    for (int mf = 0; mf < 2; mf++) {
        #pragma unroll
        for (int rs = 0; rs < 2; rs++) {
            int m = row0 + wm * 32 + mf * 16 + g + rs * 8;
            #pragma unroll
            for (int nf = 0; nf < 8; nf++) {
                int c = wcol0 + nf * 8 + t4 * 2;
                float2 r;
                r.x = acc[mf][nf][rs * 2]     + bias[c];
                r.y = acc[mf][nf][rs * 2 + 1] + bias[c + 1];
                *(float2*)&out[(size_t)m * CDIM + c] = r;
            }
        }
    }
}

// ---------------------------------------------------------------------------
extern "C" void kernel_launch(void* const* d_in, const int* in_sizes, int n_in,
                              void* d_out, int out_size)
{
    const float* x      = (const float*)d_in[0];
    const float* qkv_w  = (const float*)d_in[1];
    const float* qkv_b  = (const float*)d_in[2];
    const float* qnw    = (const float*)d_in[3];
    const float* qnb    = (const float*)d_in[4];
    const float* knw    = (const float*)d_in[5];
    const float* knb    = (const float*)d_in[6];
    const float* proj_w = (const float*)d_in[7];
    const float* pb     = (const float*)d_in[8];
    float* out = (float*)d_out;

    const int gsmem = 2 * GSTAGE * (int)sizeof(__nv_bfloat16);   // 81920
    const int fsmem = 2 * FSTAGE * (int)sizeof(__nv_bfloat16);   // 73728
    static int attr_done = 0;
    if (!attr_done) {
        cudaFuncSetAttribute(qkv_mma_kernel,  cudaFuncAttributeMaxDynamicSharedMemorySize, gsmem);
        cudaFuncSetAttribute(proj_mma_kernel, cudaFuncAttributeMaxDynamicSharedMemorySize, gsmem);
        cudaFuncSetAttribute(flash_mma_kernel, cudaFuncAttributeMaxDynamicSharedMemorySize, fsmem);
        attr_done = 1;
    }

    convert_kernel<<<2048, 256>>>(x, 0, MROWS * CDIM);
    convert_kernel<<<1024, 256>>>(qkv_w, 1, QKVN * CDIM);
    convert_kernel<<<512, 256>>>(proj_w, 2, CDIM * CDIM);

    qkv_mma_kernel<<<dim3(QKVN / 128, MROWS / 128), 256, gsmem>>>(qkv_b, qnw, qnb, knw, knb);
    flash_mma_kernel<<<dim3(NTOK / 128, BATCH * HEADS), 256, fsmem>>>();
    proj_mma_kernel<<<dim3(CDIM / 128, MROWS / 128), 256, gsmem>>>(pb, out);
}

// round 12
// speedup vs baseline: 3.3018x; 1.0459x over previous
#include <cuda_runtime.h>
#include <cuda_bf16.h>

#define BATCH 2
#define NTOK 4096
#define CDIM 1024
#define HEADS 16
#define HDIM 64
#define MROWS (BATCH * NTOK)          // 8192
#define QKVN (3 * CDIM)               // 3072
#define PHE (BATCH * HEADS * NTOK * HDIM)  // 8,388,608
#define STR 40                        // GEMM smem row stride (BK=32 + pad)
#define STRF 72                       // flash K smem row stride (64 + pad)
#define VSTR 136                      // flash V^T smem row stride (128 + pad)

// ---- static scratch ----
__device__ __align__(16) __nv_bfloat16 g_xh[MROWS * CDIM], g_xl[MROWS * CDIM];
__device__ __align__(16) __nv_bfloat16 g_wqh[QKVN * CDIM], g_wql[QKVN * CDIM];
__device__ __align__(16) __nv_bfloat16 g_wph[CDIM * CDIM], g_wpl[CDIM * CDIM];
__device__ __align__(16) __nv_bfloat16 g_qh[PHE], g_ql[PHE];
__device__ __align__(16) __nv_bfloat16 g_kh[PHE], g_kl[PHE];
__device__ __align__(16) __nv_bfloat16 g_vth[PHE], g_vtl[PHE];   // V transposed [B,H,D,N]
__device__ __align__(16) __nv_bfloat16 g_oh[MROWS * CDIM], g_ol[MROWS * CDIM];

__device__ __forceinline__ unsigned pack2(__nv_bfloat16 a, __nv_bfloat16 b) {
    __nv_bfloat162 t = __halves2bfloat162(a, b);
    return *reinterpret_cast<unsigned*>(&t);
}

__device__ __forceinline__ void mma16816(float c[4], const unsigned a[4], const unsigned b[2]) {
    asm volatile(
        "mma.sync.aligned.m16n8k16.row.col.f32.bf16.bf16.f32 "
        "{%0,%1,%2,%3}, {%4,%5,%6,%7}, {%8,%9}, {%0,%1,%2,%3};\n"
        : "+f"(c[0]), "+f"(c[1]), "+f"(c[2]), "+f"(c[3])
        : "r"(a[0]), "r"(a[1]), "r"(a[2]), "r"(a[3]), "r"(b[0]), "r"(b[1]));
}

__device__ __forceinline__ void cpa16(__nv_bfloat16* smem, const __nv_bfloat16* gmem) {
    unsigned s = (unsigned)__cvta_generic_to_shared(smem);
    asm volatile("cp.async.cg.shared.global [%0], [%1], 16;\n" :: "r"(s), "l"(gmem));
}
#define CPA_COMMIT() asm volatile("cp.async.commit_group;\n" ::: "memory")
#define CPA_WAIT1()  asm volatile("cp.async.wait_group 1;\n" ::: "memory")

__device__ __forceinline__ float fex2(float x) {
    float y;
    asm("ex2.approx.ftz.f32 %0, %1;" : "=f"(y) : "f"(x));
    return y;
}

// ---------------------------------------------------------------------------
__global__ void convert_kernel(const float* __restrict__ src, int which, int n) {
    __nv_bfloat16 *h, *l;
    if (which == 0)      { h = g_xh;  l = g_xl;  }
    else if (which == 1) { h = g_wqh; l = g_wql; }
    else                 { h = g_wph; l = g_wpl; }
    for (int i = blockIdx.x * blockDim.x + threadIdx.x; i < n;
         i += gridDim.x * blockDim.x) {
        float x = src[i];
        __nv_bfloat16 hi = __float2bfloat16(x);
        h[i] = hi;
        l[i] = __float2bfloat16(x - __bfloat162float(hi));
    }
}

// ---------------------------------------------------------------------------
// QKV GEMM (bf16x3, mma.sync, cp.async 2-stage) + bias + fused per-head LN.
// ---------------------------------------------------------------------------
#define GSTG (128 * STR)           // 5120
#define GSTAGE (4 * GSTG)          // 20480 elems = 40960 B

__global__ __launch_bounds__(256, 2) void qkv_mma_kernel(
    const float* __restrict__ bias,
    const float* __restrict__ qnw, const float* __restrict__ qnb,
    const float* __restrict__ knw, const float* __restrict__ knb)
{
    extern __shared__ __align__(16) __nv_bfloat16 dyn[];

    const int tid = threadIdx.x;
    const int lane = tid & 31, wid = tid >> 5;
    const int wm = wid & 3, wn = wid >> 2;
    const int g = lane >> 2, t4 = lane & 3;
    const int row0 = blockIdx.y * 128;
    const int col0 = blockIdx.x * 128;

    const int lr0 = tid >> 2, lc0 = (tid & 3) * 8;
    const int lr1 = (256 + tid) >> 2, lc1 = lc0;

    float acc[2][8][4];
    #pragma unroll
    for (int i = 0; i < 2; i++)
        #pragma unroll
        for (int j = 0; j < 8; j++)
            #pragma unroll
            for (int c = 0; c < 4; c++) acc[i][j][c] = 0.f;

    {
        __nv_bfloat16* s = dyn;
        cpa16(&s[0 * GSTG + lr0 * STR + lc0], &g_xh [(size_t)(row0 + lr0) * CDIM + lc0]);
        cpa16(&s[0 * GSTG + lr1 * STR + lc1], &g_xh [(size_t)(row0 + lr1) * CDIM + lc1]);
        cpa16(&s[1 * GSTG + lr0 * STR + lc0], &g_xl [(size_t)(row0 + lr0) * CDIM + lc0]);
        cpa16(&s[1 * GSTG + lr1 * STR + lc1], &g_xl [(size_t)(row0 + lr1) * CDIM + lc1]);
        cpa16(&s[2 * GSTG + lr0 * STR + lc0], &g_wqh[(size_t)(col0 + lr0) * CDIM + lc0]);
        cpa16(&s[2 * GSTG + lr1 * STR + lc1], &g_wqh[(size_t)(col0 + lr1) * CDIM + lc1]);
        cpa16(&s[3 * GSTG + lr0 * STR + lc0], &g_wql[(size_t)(col0 + lr0) * CDIM + lc0]);
        cpa16(&s[3 * GSTG + lr1 * STR + lc1], &g_wql[(size_t)(col0 + lr1) * CDIM + lc1]);
        CPA_COMMIT();
    }

    for (int kt = 0; kt < CDIM / 32; kt++) {
        __syncthreads();
        if (kt + 1 < CDIM / 32) {
            __nv_bfloat16* s = dyn + ((kt + 1) & 1) * GSTAGE;
            int k0 = (kt + 1) * 32;
            cpa16(&s[0 * GSTG + lr0 * STR + lc0], &g_xh [(size_t)(row0 + lr0) * CDIM + k0 + lc0]);
            cpa16(&s[0 * GSTG + lr1 * STR + lc1], &g_xh [(size_t)(row0 + lr1) * CDIM + k0 + lc1]);
            cpa16(&s[1 * GSTG + lr0 * STR + lc0], &g_xl [(size_t)(row0 + lr0) * CDIM + k0 + lc0]);
            cpa16(&s[1 * GSTG + lr1 * STR + lc1], &g_xl [(size_t)(row0 + lr1) * CDIM + k0 + lc1]);
            cpa16(&s[2 * GSTG + lr0 * STR + lc0], &g_wqh[(size_t)(col0 + lr0) * CDIM + k0 + lc0]);
            cpa16(&s[2 * GSTG + lr1 * STR + lc1], &g_wqh[(size_t)(col0 + lr1) * CDIM + k0 + lc1]);
            cpa16(&s[3 * GSTG + lr0 * STR + lc0], &g_wql[(size_t)(col0 + lr0) * CDIM + k0 + lc0]);
            cpa16(&s[3 * GSTG + lr1 * STR + lc1], &g_wql[(size_t)(col0 + lr1) * CDIM + k0 + lc1]);
        }
        CPA_COMMIT();
        CPA_WAIT1();
        __syncthreads();

        const __nv_bfloat16* pAh = dyn + (kt & 1) * GSTAGE;
        const __nv_bfloat16* pAl = pAh + GSTG;
        const __nv_bfloat16* pBh = pAl + GSTG;
        const __nv_bfloat16* pBl = pBh + GSTG;

        #pragma unroll
        for (int ks = 0; ks < 2; ks++) {
            unsigned ah[2][4], al[2][4];
            #pragma unroll
            for (int mf = 0; mf < 2; mf++) {
                int base = (wm * 32 + mf * 16 + g) * STR + ks * 16 + t4 * 2;
                ah[mf][0] = *(const unsigned*)&pAh[base];
                ah[mf][1] = *(const unsigned*)&pAh[base + 8 * STR];
                ah[mf][2] = *(const unsigned*)&pAh[base + 8];
                ah[mf][3] = *(const unsigned*)&pAh[base + 8 * STR + 8];
                al[mf][0] = *(const unsigned*)&pAl[base];
                al[mf][1] = *(const unsigned*)&pAl[base + 8 * STR];
                al[mf][2] = *(const unsigned*)&pAl[base + 8];
                al[mf][3] = *(const unsigned*)&pAl[base + 8 * STR + 8];
            }
            #pragma unroll
            for (int nf = 0; nf < 8; nf++) {
                int base = (wn * 64 + nf * 8 + g) * STR + ks * 16 + t4 * 2;
                unsigned bh[2] = {*(const unsigned*)&pBh[base], *(const unsigned*)&pBh[base + 8]};
                unsigned bl[2] = {*(const unsigned*)&pBl[base], *(const unsigned*)&pBl[base + 8]};
                #pragma unroll
                for (int mf = 0; mf < 2; mf++) {
                    mma16816(acc[mf][nf], ah[mf], bh);
                    mma16816(acc[mf][nf], al[mf], bh);
                    mma16816(acc[mf][nf], ah[mf], bl);
                }
            }
        }
    }

    const int wcol0 = col0 + wn * 64;
    #pragma unroll
    for (int nf = 0; nf < 8; nf++) {
        int c = wcol0 + nf * 8 + t4 * 2;
        float b0 = bias[c], b1 = bias[c + 1];
        #pragma unroll
        for (int mf = 0; mf < 2; mf++) {
            acc[mf][nf][0] += b0; acc[mf][nf][1] += b1;
            acc[mf][nf][2] += b0; acc[mf][nf][3] += b1;
        }
    }

    const int part = col0 >> 10;
    const int h = (wcol0 & 1023) >> 6;
    // q: fold D^-0.5 AND log2(e) so flash can use raw ex2
    const float sc = (part == 0) ? (0.125f * 1.44269504f) : 1.0f;

    #pragma unroll
    for (int mf = 0; mf < 2; mf++) {
        #pragma unroll
        for (int rs = 0; rs < 2; rs++) {
            float v[16];
            #pragma unroll
            for (int nf = 0; nf < 8; nf++) {
                v[2 * nf]     = acc[mf][nf][rs * 2];
                v[2 * nf + 1] = acc[mf][nf][rs * 2 + 1];
            }
            if (part < 2) {
                const float* nw = (part == 0) ? qnw : knw;
                const float* nb = (part == 0) ? qnb : knb;
                float s = 0.f;
                #pragma unroll
                for (int j = 0; j < 16; j++) s += v[j];
                s += __shfl_xor_sync(0xffffffffu, s, 1, 4);
                s += __shfl_xor_sync(0xffffffffu, s, 2, 4);
                float mean = s * (1.0f / 64.0f);
                float sq = 0.f;
                #pragma unroll
                for (int j = 0; j < 16; j++) { float d = v[j] - mean; sq += d * d; }
                sq += __shfl_xor_sync(0xffffffffu, sq, 1, 4);
                sq += __shfl_xor_sync(0xffffffffu, sq, 2, 4);
                float inv = rsqrtf(sq * (1.0f / 64.0f) + 1e-5f);
                #pragma unroll
                for (int j = 0; j < 16; j++) {
                    int dcol = (j >> 1) * 8 + t4 * 2 + (j & 1);
                    v[j] = ((v[j] - mean) * inv * nw[dcol] + nb[dcol]) * sc;
                }
            }
            int m = row0 + wm * 32 + mf * 16 + g + rs * 8;
            int bb = m >> 12, t = m & 4095;
            if (part < 2) {
                __nv_bfloat16* dh = (part == 0) ? g_qh : g_kh;
                __nv_bfloat16* dl = (part == 0) ? g_ql : g_kl;
                size_t base = ((size_t)(bb * HEADS + h) * NTOK + t) * HDIM;
                #pragma unroll
                for (int nf = 0; nf < 8; nf++) {
                    int d = nf * 8 + t4 * 2;
                    float v0 = v[2 * nf], v1 = v[2 * nf + 1];
                    __nv_bfloat16 h0 = __float2bfloat16(v0);
                    __nv_bfloat16 h1 = __float2bfloat16(v1);
                    *(unsigned*)&dh[base + d] = pack2(h0, h1);
                    *(unsigned*)&dl[base + d] =
                        pack2(__float2bfloat16(v0 - __bfloat162float(h0)),
                              __float2bfloat16(v1 - __bfloat162float(h1)));
                }
            } else {
                size_t vbase = (size_t)(bb * HEADS + h) * HDIM * NTOK + t;
                #pragma unroll
                for (int nf = 0; nf < 8; nf++) {
                    int d = nf * 8 + t4 * 2;
                    float v0 = v[2 * nf], v1 = v[2 * nf + 1];
                    __nv_bfloat16 h0 = __float2bfloat16(v0);
                    __nv_bfloat16 h1 = __float2bfloat16(v1);
                    g_vth[vbase + (size_t)d * NTOK]       = h0;
                    g_vth[vbase + (size_t)(d + 1) * NTOK] = h1;
                    g_vtl[vbase + (size_t)d * NTOK]       = __float2bfloat16(v0 - __bfloat162float(h0));
                    g_vtl[vbase + (size_t)(d + 1) * NTOK] = __float2bfloat16(v1 - __bfloat162float(h1));
                }
            }
        }
    }
}

// ---------------------------------------------------------------------------
// Flash attention (bf16x3, cp.async 2-stage, KEY TILE 128, NO online max).
// Scores are LN-bounded -> plain exp2 accumulate; l reduced once at epilogue.
// Stage layout (bf16): [Kh 9216][Kl 9216][Vth 8704][Vtl 8704] = 35840 elems.
// ---------------------------------------------------------------------------
#define KT 128
#define NKT (NTOK / KT)             // 32
#define FK (KT * STRF)              // 9216
#define FV (HDIM * VSTR)            // 8704
#define FSTAGE (2 * FK + 2 * FV)    // 35840 elems = 71680 B

__global__ __launch_bounds__(256) void flash_mma_kernel()
{
    extern __shared__ __align__(16) __nv_bfloat16 fdyn[];

    const int tid = threadIdx.x;
    const int lane = tid & 31, wid = tid >> 5;
    const int g = lane >> 2, t4 = lane & 3;
    const int qb = blockIdx.x, bh = blockIdx.y;

    const size_t hbase = (size_t)bh * NTOK * HDIM;   // q/k [bh][t][d]
    const size_t vbase = (size_t)bh * HDIM * NTOK;   // vT  [bh][d][t]
    const int qrow = qb * 128 + wid * 16;

    // Q fragments resident
    unsigned qh[4][4], ql[4][4];
    {
        const __nv_bfloat16* Ph = g_qh + hbase + (size_t)qrow * HDIM;
        const __nv_bfloat16* Pl = g_ql + hbase + (size_t)qrow * HDIM;
        #pragma unroll
        for (int ks = 0; ks < 4; ks++) {
            int c = ks * 16 + t4 * 2;
            qh[ks][0] = *(const unsigned*)&Ph[g * HDIM + c];
            qh[ks][1] = *(const unsigned*)&Ph[(g + 8) * HDIM + c];
            qh[ks][2] = *(const unsigned*)&Ph[g * HDIM + c + 8];
            qh[ks][3] = *(const unsigned*)&Ph[(g + 8) * HDIM + c + 8];
            ql[ks][0] = *(const unsigned*)&Pl[g * HDIM + c];
            ql[ks][1] = *(const unsigned*)&Pl[(g + 8) * HDIM + c];
            ql[ks][2] = *(const unsigned*)&Pl[g * HDIM + c + 8];
            ql[ks][3] = *(const unsigned*)&Pl[(g + 8) * HDIM + c + 8];
        }
    }

    float o[8][4];
    #pragma unroll
    for (int i = 0; i < 8; i++)
        #pragma unroll
        for (int c = 0; c < 4; c++) o[i][c] = 0.f;
    float lrow[2] = {0.f, 0.f};

    // tile loader (16 cp.async per thread)
    auto load_tile = [&](int kt, int buf) {
        __nv_bfloat16* s = fdyn + buf * FSTAGE;
        size_t koff = hbase + (size_t)kt * KT * HDIM;
        size_t voff = vbase + (size_t)kt * KT;
        #pragma unroll
        for (int it = 0; it < 4; it++) {
            int idx = it * 256 + tid;
            int kr = idx >> 3, kc = (idx & 7) * 8;
            cpa16(&s[kr * STRF + kc],      &g_kh [koff + (size_t)kr * HDIM + kc]);
            cpa16(&s[FK + kr * STRF + kc], &g_kl [koff + (size_t)kr * HDIM + kc]);
            int vr = idx >> 4, vc = (idx & 15) * 8;
            cpa16(&s[2 * FK + vr * VSTR + vc],      &g_vth[voff + (size_t)vr * NTOK + vc]);
            cpa16(&s[2 * FK + FV + vr * VSTR + vc], &g_vtl[voff + (size_t)vr * NTOK + vc]);
        }
    };

    load_tile(0, 0);
    CPA_COMMIT();

    for (int kt = 0; kt < NKT; kt++) {
        __syncthreads();
        if (kt + 1 < NKT) load_tile(kt + 1, (kt + 1) & 1);
        CPA_COMMIT();
        CPA_WAIT1();
        __syncthreads();

        const __nv_bfloat16* pKh = fdyn + (kt & 1) * FSTAGE;
        const __nv_bfloat16* pKl = pKh + FK;
        const __nv_bfloat16* pVh = pKh + 2 * FK;
        const __nv_bfloat16* pVl = pVh + FV;

        // S = Q K^T  (16 key-groups of 8)
        float s[16][4];
        #pragma unroll
        for (int i = 0; i < 16; i++)
            #pragma unroll
            for (int c = 0; c < 4; c++) s[i][c] = 0.f;
        #pragma unroll
        for (int ks = 0; ks < 4; ks++) {
            #pragma unroll
            for (int nf = 0; nf < 16; nf++) {
                int base = (nf * 8 + g) * STRF + ks * 16 + t4 * 2;
                unsigned kbh[2] = {*(const unsigned*)&pKh[base], *(const unsigned*)&pKh[base + 8]};
                unsigned kbl[2] = {*(const unsigned*)&pKl[base], *(const unsigned*)&pKl[base + 8]};
                mma16816(s[nf], qh[ks], kbh);
                mma16816(s[nf], ql[ks], kbh);
                mma16816(s[nf], qh[ks], kbl);
            }
        }

        // P = exp2(S) (q pre-scaled by log2e); accumulate per-thread l partials
        #pragma unroll
        for (int nf = 0; nf < 16; nf++) {
            float p0 = fex2(s[nf][0]);
            float p1 = fex2(s[nf][1]);
            float p2 = fex2(s[nf][2]);
            float p3 = fex2(s[nf][3]);
            s[nf][0] = p0; s[nf][1] = p1; s[nf][2] = p2; s[nf][3] = p3;
            lrow[0] += p0 + p1;
            lrow[1] += p2 + p3;
        }

        // O += P V  (8 k-steps over 128 keys; V B-frags = b32 loads from V^T)
        #pragma unroll
        for (int ks = 0; ks < 8; ks++) {
            unsigned pah[4], pal[4];
            {
                float p0 = s[2 * ks][0], p1 = s[2 * ks][1];
                float p2 = s[2 * ks][2], p3 = s[2 * ks][3];
                float p4 = s[2 * ks + 1][0], p5 = s[2 * ks + 1][1];
                float p6 = s[2 * ks + 1][2], p7 = s[2 * ks + 1][3];
                __nv_bfloat16 h0 = __float2bfloat16(p0), h1 = __float2bfloat16(p1);
                __nv_bfloat16 h2 = __float2bfloat16(p2), h3 = __float2bfloat16(p3);
                __nv_bfloat16 h4 = __float2bfloat16(p4), h5 = __float2bfloat16(p5);
                __nv_bfloat16 h6 = __float2bfloat16(p6), h7 = __float2bfloat16(p7);
                pah[0] = pack2(h0, h1); pah[1] = pack2(h2, h3);
                pah[2] = pack2(h4, h5); pah[3] = pack2(h6, h7);
                pal[0] = pack2(__float2bfloat16(p0 - __bfloat162float(h0)),
                               __float2bfloat16(p1 - __bfloat162float(h1)));
                pal[1] = pack2(__float2bfloat16(p2 - __bfloat162float(h2)),
                               __float2bfloat16(p3 - __bfloat162float(h3)));
                pal[2] = pack2(__float2bfloat16(p4 - __bfloat162float(h4)),
                               __float2bfloat16(p5 - __bfloat162float(h5)));
                pal[3] = pack2(__float2bfloat16(p6 - __bfloat162float(h6)),
                               __float2bfloat16(p7 - __bfloat162float(h7)));
            }
            #pragma unroll
            for (int nfd = 0; nfd < 8; nfd++) {
                int n = nfd * 8 + g;
                int k0 = ks * 16 + t4 * 2;
                unsigned vbh[2] = {*(const unsigned*)&pVh[n * VSTR + k0],
                                   *(const unsigned*)&pVh[n * VSTR + k0 + 8]};
                unsigned vbl[2] = {*(const unsigned*)&pVl[n * VSTR + k0],
                                   *(const unsigned*)&pVl[n * VSTR + k0 + 8]};
                mma16816(o[nfd], pah, vbh);
                mma16816(o[nfd], pal, vbh);
                mma16816(o[nfd], pah, vbl);
            }
        }
    }

    // epilogue: reduce l across the quad once, normalize, write O hi/lo
    lrow[0] += __shfl_xor_sync(0xffffffffu, lrow[0], 1, 4);
    lrow[0] += __shfl_xor_sync(0xffffffffu, lrow[0], 2, 4);
    lrow[1] += __shfl_xor_sync(0xffffffffu, lrow[1], 1, 4);
    lrow[1] += __shfl_xor_sync(0xffffffffu, lrow[1], 2, 4);

    const int bb = bh >> 4, hh = bh & 15;
    #pragma unroll
    for (int rs = 0; rs < 2; rs++) {
        float inv = 1.0f / lrow[rs];
        int t = qrow + g + rs * 8;
        size_t base = ((size_t)(bb * NTOK + t)) * CDIM + hh * HDIM;
        #pragma unroll
        for (int nfd = 0; nfd < 8; nfd++) {
            int d = nfd * 8 + t4 * 2;
            float v0 = o[nfd][rs * 2] * inv;
            float v1 = o[nfd][rs * 2 + 1] * inv;
            __nv_bfloat16 h0 = __float2bfloat16(v0);
            __nv_bfloat16 h1 = __float2bfloat16(v1);
            *(unsigned*)&g_oh[base + d] = pack2(h0, h1);
            *(unsigned*)&g_ol[base + d] =
                pack2(__float2bfloat16(v0 - __bfloat162float(h0)),
                      __float2bfloat16(v1 - __bfloat162float(h1)));
        }
    }
}

// ---------------------------------------------------------------------------
// Output projection GEMM (bf16x3, cp.async 2-stage) + bias -> fp32 d_out
// ---------------------------------------------------------------------------
__global__ __launch_bounds__(256, 2) void proj_mma_kernel(
    const float* __restrict__ bias, float* __restrict__ out)
{
    extern __shared__ __align__(16) __nv_bfloat16 dyn[];

    const int tid = threadIdx.x;
    const int lane = tid & 31, wid = tid >> 5;
    const int wm = wid & 3, wn = wid >> 2;
    const int g = lane >> 2, t4 = lane & 3;
    const int row0 = blockIdx.y * 128;
    const int col0 = blockIdx.x * 128;

    const int lr0 = tid >> 2, lc0 = (tid & 3) * 8;
    const int lr1 = (256 + tid) >> 2, lc1 = lc0;

    float acc[2][8][4];
    #pragma unroll
    for (int i = 0; i < 2; i++)
        #pragma unroll
        for (int j = 0; j < 8; j++)
            #pragma unroll
            for (int c = 0; c < 4; c++) acc[i][j][c] = 0.f;

    {
        __nv_bfloat16* s = dyn;
        cpa16(&s[0 * GSTG + lr0 * STR + lc0], &g_oh [(size_t)(row0 + lr0) * CDIM + lc0]);
        cpa16(&s[0 * GSTG + lr1 * STR + lc1], &g_oh [(size_t)(row0 + lr1) * CDIM + lc1]);
        cpa16(&s[1 * GSTG + lr0 * STR + lc0], &g_ol [(size_t)(row0 + lr0) * CDIM + lc0]);
        cpa16(&s[1 * GSTG + lr1 * STR + lc1], &g_ol [(size_t)(row0 + lr1) * CDIM + lc1]);
        cpa16(&s[2 * GSTG + lr0 * STR + lc0], &g_wph[(size_t)(col0 + lr0) * CDIM + lc0]);
        cpa16(&s[2 * GSTG + lr1 * STR + lc1], &g_wph[(size_t)(col0 + lr1) * CDIM + lc1]);
        cpa16(&s[3 * GSTG + lr0 * STR + lc0], &g_wpl[(size_t)(col0 + lr0) * CDIM + lc0]);
        cpa16(&s[3 * GSTG + lr1 * STR + lc1], &g_wpl[(size_t)(col0 + lr1) * CDIM + lc1]);
        CPA_COMMIT();
    }

    for (int kt = 0; kt < CDIM / 32; kt++) {
        __syncthreads();
        if (kt + 1 < CDIM / 32) {
            __nv_bfloat16* s = dyn + ((kt + 1) & 1) * GSTAGE;
            int k0 = (kt + 1) * 32;
            cpa16(&s[0 * GSTG + lr0 * STR + lc0], &g_oh [(size_t)(row0 + lr0) * CDIM + k0 + lc0]);
            cpa16(&s[0 * GSTG + lr1 * STR + lc1], &g_oh [(size_t)(row0 + lr1) * CDIM + k0 + lc1]);
            cpa16(&s[1 * GSTG + lr0 * STR + lc0], &g_ol [(size_t)(row0 + lr0) * CDIM + k0 + lc0]);
            cpa16(&s[1 * GSTG + lr1 * STR + lc1], &g_ol [(size_t)(row0 + lr1) * CDIM + k0 + lc1]);
            cpa16(&s[2 * GSTG + lr0 * STR + lc0], &g_wph[(size_t)(col0 + lr0) * CDIM + k0 + lc0]);
            cpa16(&s[2 * GSTG + lr1 * STR + lc1], &g_wph[(size_t)(col0 + lr1) * CDIM + k0 + lc1]);
            cpa16(&s[3 * GSTG + lr0 * STR + lc0], &g_wpl[(size_t)(col0 + lr0) * CDIM + k0 + lc0]);
            cpa16(&s[3 * GSTG + lr1 * STR + lc1], &g_wpl[(size_t)(col0 + lr1) * CDIM + k0 + lc1]);
        }
        CPA_COMMIT();
        CPA_WAIT1();
        __syncthreads();

        const __nv_bfloat16* pAh = dyn + (kt & 1) * GSTAGE;
        const __nv_bfloat16* pAl = pAh + GSTG;
        const __nv_bfloat16* pBh = pAl + GSTG;
        const __nv_bfloat16* pBl = pBh + GSTG;

        #pragma unroll
        for (int ks = 0; ks < 2; ks++) {
            unsigned ah[2][4], al[2][4];
            #pragma unroll
            for (int mf = 0; mf < 2; mf++) {
                int base = (wm * 32 + mf * 16 + g) * STR + ks * 16 + t4 * 2;
                ah[mf][0] = *(const unsigned*)&pAh[base];
                ah[mf][1] = *(const unsigned*)&pAh[base + 8 * STR];
                ah[mf][2] = *(const unsigned*)&pAh[base + 8];
                ah[mf][3] = *(const unsigned*)&pAh[base + 8 * STR + 8];
                al[mf][0] = *(const unsigned*)&pAl[base];
                al[mf][1] = *(const unsigned*)&pAl[base + 8 * STR];
                al[mf][2] = *(const unsigned*)&pAl[base + 8];
                al[mf][3] = *(const unsigned*)&pAl[base + 8 * STR + 8];
            }
            #pragma unroll
            for (int nf = 0; nf < 8; nf++) {
                int base = (wn * 64 + nf * 8 + g) * STR + ks * 16 + t4 * 2;
                unsigned bh[2] = {*(const unsigned*)&pBh[base], *(const unsigned*)&pBh[base + 8]};
                unsigned bl[2] = {*(const unsigned*)&pBl[base], *(const unsigned*)&pBl[base + 8]};
                #pragma unroll
                for (int mf = 0; mf < 2; mf++) {
                    mma16816(acc[mf][nf], ah[mf], bh);
                    mma16816(acc[mf][nf], al[mf], bh);
                    mma16816(acc[mf][nf], ah[mf], bl);
                }
            }
        }
    }

    const int wcol0 = col0 + wn * 64;
    #pragma unroll
    for (int mf = 0; mf < 2; mf++) {
        #pragma unroll
        for (int rs = 0; rs < 2; rs++) {
            int m = row0 + wm * 32 + mf * 16 + g + rs * 8;
            #pragma unroll
            for (int nf = 0; nf < 8; nf++) {
                int c = wcol0 + nf * 8 + t4 * 2;
                float2 r;
                r.x = acc[mf][nf][rs * 2]     + bias[c];
                r.y = acc[mf][nf][rs * 2 + 1] + bias[c + 1];
                *(float2*)&out[(size_t)m * CDIM + c] = r;
            }
        }
    }
}

// ---------------------------------------------------------------------------
extern "C" void kernel_launch(void* const* d_in, const int* in_sizes, int n_in,
                              void* d_out, int out_size)
{
    const float* x      = (const float*)d_in[0];
    const float* qkv_w  = (const float*)d_in[1];
    const float* qkv_b  = (const float*)d_in[2];
    const float* qnw    = (const float*)d_in[3];
    const float* qnb    = (const float*)d_in[4];
    const float* knw    = (const float*)d_in[5];
    const float* knb    = (const float*)d_in[6];
    const float* proj_w = (const float*)d_in[7];
    const float* pb     = (const float*)d_in[8];
    float* out = (float*)d_out;

    const int gsmem = 2 * GSTAGE * (int)sizeof(__nv_bfloat16);   // 81920
    const int fsmem = 2 * FSTAGE * (int)sizeof(__nv_bfloat16);   // 143360
    static int attr_done = 0;
    if (!attr_done) {
        cudaFuncSetAttribute(qkv_mma_kernel,  cudaFuncAttributeMaxDynamicSharedMemorySize, gsmem);
        cudaFuncSetAttribute(proj_mma_kernel, cudaFuncAttributeMaxDynamicSharedMemorySize, gsmem);
        cudaFuncSetAttribute(flash_mma_kernel, cudaFuncAttributeMaxDynamicSharedMemorySize, fsmem);
        attr_done = 1;
    }

    convert_kernel<<<2048, 256>>>(x, 0, MROWS * CDIM);
    convert_kernel<<<1024, 256>>>(qkv_w, 1, QKVN * CDIM);
    convert_kernel<<<512, 256>>>(proj_w, 2, CDIM * CDIM);

    qkv_mma_kernel<<<dim3(QKVN / 128, MROWS / 128), 256, gsmem>>>(qkv_b, qnw, qnb, knw, knb);
    flash_mma_kernel<<<dim3(NTOK / 128, BATCH * HEADS), 256, fsmem>>>();
    proj_mma_kernel<<<dim3(CDIM / 128, MROWS / 128), 256, gsmem>>>(pb, out);
}

// round 17
// speedup vs baseline: 4.2015x; 1.2725x over previous
#include <cuda_runtime.h>
#include <cuda_fp16.h>
#include <cstdint>

#define BATCH 2
#define NTOK 4096
#define CDIM 1024
#define HEADS 16
#define HDIM 64
#define MROWS (BATCH * NTOK)          // 8192
#define QKVN (3 * CDIM)               // 3072
#define PHE (BATCH * HEADS * NTOK * HDIM)  // 8,388,608
#define STR 40                        // GEMM smem row stride (BK=32 + pad)
#define STRF 72                       // flash K smem row stride (64 + pad)
#define VSTR 136                      // flash V^T smem row stride (128 + pad)

// ---- static scratch (fp16) ----
// scheme: products use x2 split on the "data" side (x, q, v, o); the other
// side (weights, k, p) is single fp16 (truncation rel-err ~2^-13 per stage).
__device__ __align__(16) __half g_xh[MROWS * CDIM], g_xl[MROWS * CDIM];
__device__ __align__(16) __half g_wqh[QKVN * CDIM];           // qkv weight, hi only
__device__ __align__(16) __half g_wph[CDIM * CDIM];           // proj weight, hi only
__device__ __align__(16) __half g_qh[PHE], g_ql[PHE];         // q x2 (corrected in QK)
__device__ __align__(16) __half g_kh[PHE];                    // k hi only
__device__ __align__(16) __half g_vth[PHE], g_vtl[PHE];       // V^T x2 (corrected in PV)
__device__ __align__(16) __half g_oh[MROWS * CDIM], g_ol[MROWS * CDIM];  // O x2

__device__ __forceinline__ unsigned pack2h(__half a, __half b) {
    __half2 t = __halves2half2(a, b);   // a -> low 16 bits
    return *reinterpret_cast<unsigned*>(&t);
}

__device__ __forceinline__ void mma16816(float c[4], const unsigned a[4], const unsigned b[2]) {
    asm volatile(
        "mma.sync.aligned.m16n8k16.row.col.f32.f16.f16.f32 "
        "{%0,%1,%2,%3}, {%4,%5,%6,%7}, {%8,%9}, {%0,%1,%2,%3};\n"
        : "+f"(c[0]), "+f"(c[1]), "+f"(c[2]), "+f"(c[3])
        : "r"(a[0]), "r"(a[1]), "r"(a[2]), "r"(a[3]), "r"(b[0]), "r"(b[1]));
}

__device__ __forceinline__ void cpa16(__half* smem, const __half* gmem) {
    unsigned s = (unsigned)__cvta_generic_to_shared(smem);
    asm volatile("cp.async.cg.shared.global [%0], [%1], 16;\n" :: "r"(s), "l"(gmem));
}
#define CPA_COMMIT() asm volatile("cp.async.commit_group;\n" ::: "memory")
#define CPA_WAIT1()  asm volatile("cp.async.wait_group 1;\n" ::: "memory")

__device__ __forceinline__ float fex2(float x) {
    float y;
    asm("ex2.approx.ftz.f32 %0, %1;" : "=f"(y) : "f"(x));
    return y;
}

__device__ __forceinline__ void split2(float v, __half& h, __half& l) {
    h = __float2half(v);
    l = __float2half(v - __half2float(h));
}

// ---------------------------------------------------------------------------
// fp32 -> fp16 split (x: hi+lo) / truncate (weights: hi only)
// ---------------------------------------------------------------------------
__global__ void convert_kernel(const float* __restrict__ src, int which, int n) {
    if (which == 0) {
        for (int i = blockIdx.x * blockDim.x + threadIdx.x; i < n;
             i += gridDim.x * blockDim.x) {
            float x = src[i];
            __half hi, lo;
            split2(x, hi, lo);
            g_xh[i] = hi;
            g_xl[i] = lo;
        }
    } else {
        __half* h = (which == 1) ? g_wqh : g_wph;
        for (int i = blockIdx.x * blockDim.x + threadIdx.x; i < n;
             i += gridDim.x * blockDim.x)
            h[i] = __float2half(src[i]);
    }
}

// ---------------------------------------------------------------------------
// QKV GEMM (fp16 x2, mma.sync, cp.async 2-stage) + bias + fused per-head LN.
// Block 128x128, BK=32, 8 warps 4(m)x2(n). Stage: [Ah 5120][Al 5120][Bh 5120].
// ---------------------------------------------------------------------------
#define GSTG (128 * STR)           // 5120
#define GSTAGE (3 * GSTG)          // 15360 elems = 30720 B

__global__ __launch_bounds__(256, 2) void qkv_mma_kernel(
    const float* __restrict__ bias,
    const float* __restrict__ qnw, const float* __restrict__ qnb,
    const float* __restrict__ knw, const float* __restrict__ knb)
{
    extern __shared__ __align__(16) __half dyn[];

    const int tid = threadIdx.x;
    const int lane = tid & 31, wid = tid >> 5;
    const int wm = wid & 3, wn = wid >> 2;
    const int g = lane >> 2, t4 = lane & 3;
    const int row0 = blockIdx.y * 128;
    const int col0 = blockIdx.x * 128;

    const int lr0 = tid >> 2, lc0 = (tid & 3) * 8;
    const int lr1 = (256 + tid) >> 2, lc1 = lc0;

    float acc[2][8][4];
    #pragma unroll
    for (int i = 0; i < 2; i++)
        #pragma unroll
        for (int j = 0; j < 8; j++)
            #pragma unroll
            for (int c = 0; c < 4; c++) acc[i][j][c] = 0.f;

    auto load_stage = [&](int kt, int st) {
        __half* s = dyn + st * GSTAGE;
        int k0 = kt * 32;
        cpa16(&s[0 * GSTG + lr0 * STR + lc0], &g_xh [(size_t)(row0 + lr0) * CDIM + k0 + lc0]);
        cpa16(&s[0 * GSTG + lr1 * STR + lc1], &g_xh [(size_t)(row0 + lr1) * CDIM + k0 + lc1]);
        cpa16(&s[1 * GSTG + lr0 * STR + lc0], &g_xl [(size_t)(row0 + lr0) * CDIM + k0 + lc0]);
        cpa16(&s[1 * GSTG + lr1 * STR + lc1], &g_xl [(size_t)(row0 + lr1) * CDIM + k0 + lc1]);
        cpa16(&s[2 * GSTG + lr0 * STR + lc0], &g_wqh[(size_t)(col0 + lr0) * CDIM + k0 + lc0]);
        cpa16(&s[2 * GSTG + lr1 * STR + lc1], &g_wqh[(size_t)(col0 + lr1) * CDIM + k0 + lc1]);
    };

    load_stage(0, 0);
    CPA_COMMIT();

    for (int kt = 0; kt < CDIM / 32; kt++) {
        __syncthreads();
        if (kt + 1 < CDIM / 32) load_stage(kt + 1, (kt + 1) & 1);
        CPA_COMMIT();
        CPA_WAIT1();
        __syncthreads();

        const __half* pAh = dyn + (kt & 1) * GSTAGE;
        const __half* pAl = pAh + GSTG;
        const __half* pBh = pAl + GSTG;

        #pragma unroll
        for (int ks = 0; ks < 2; ks++) {
            unsigned ah[2][4], al[2][4];
            #pragma unroll
            for (int mf = 0; mf < 2; mf++) {
                int base = (wm * 32 + mf * 16 + g) * STR + ks * 16 + t4 * 2;
                ah[mf][0] = *(const unsigned*)&pAh[base];
                ah[mf][1] = *(const unsigned*)&pAh[base + 8 * STR];
                ah[mf][2] = *(const unsigned*)&pAh[base + 8];
                ah[mf][3] = *(const unsigned*)&pAh[base + 8 * STR + 8];
                al[mf][0] = *(const unsigned*)&pAl[base];
                al[mf][1] = *(const unsigned*)&pAl[base + 8 * STR];
                al[mf][2] = *(const unsigned*)&pAl[base + 8];
                al[mf][3] = *(const unsigned*)&pAl[base + 8 * STR + 8];
            }
            #pragma unroll
            for (int nf = 0; nf < 8; nf++) {
                int base = (wn * 64 + nf * 8 + g) * STR + ks * 16 + t4 * 2;
                unsigned bh[2] = {*(const unsigned*)&pBh[base], *(const unsigned*)&pBh[base + 8]};
                #pragma unroll
                for (int mf = 0; mf < 2; mf++) {
                    mma16816(acc[mf][nf], ah[mf], bh);
                    mma16816(acc[mf][nf], al[mf], bh);
                }
            }
        }
    }

    const int wcol0 = col0 + wn * 64;
    #pragma unroll
    for (int nf = 0; nf < 8; nf++) {
        int c = wcol0 + nf * 8 + t4 * 2;
        float b0 = bias[c], b1 = bias[c + 1];
        #pragma unroll
        for (int mf = 0; mf < 2; mf++) {
            acc[mf][nf][0] += b0; acc[mf][nf][1] += b1;
            acc[mf][nf][2] += b0; acc[mf][nf][3] += b1;
        }
    }

    const int part = col0 >> 10;
    const int h = (wcol0 & 1023) >> 6;
    // q: fold D^-0.5 AND log2(e) so flash uses raw ex2
    const float sc = (part == 0) ? (0.125f * 1.44269504f) : 1.0f;

    #pragma unroll
    for (int mf = 0; mf < 2; mf++) {
        #pragma unroll
        for (int rs = 0; rs < 2; rs++) {
            float v[16];
            #pragma unroll
            for (int nf = 0; nf < 8; nf++) {
                v[2 * nf]     = acc[mf][nf][rs * 2];
                v[2 * nf + 1] = acc[mf][nf][rs * 2 + 1];
            }
            if (part < 2) {
                const float* nw = (part == 0) ? qnw : knw;
                const float* nb = (part == 0) ? qnb : knb;
                float s = 0.f;
                #pragma unroll
                for (int j = 0; j < 16; j++) s += v[j];
                s += __shfl_xor_sync(0xffffffffu, s, 1, 4);
                s += __shfl_xor_sync(0xffffffffu, s, 2, 4);
                float mean = s * (1.0f / 64.0f);
                float sq = 0.f;
                #pragma unroll
                for (int j = 0; j < 16; j++) { float d = v[j] - mean; sq += d * d; }
                sq += __shfl_xor_sync(0xffffffffu, sq, 1, 4);
                sq += __shfl_xor_sync(0xffffffffu, sq, 2, 4);
                float inv = rsqrtf(sq * (1.0f / 64.0f) + 1e-5f);
                #pragma unroll
                for (int j = 0; j < 16; j++) {
                    int dcol = (j >> 1) * 8 + t4 * 2 + (j & 1);
                    v[j] = ((v[j] - mean) * inv * nw[dcol] + nb[dcol]) * sc;
                }
            }
            int m = row0 + wm * 32 + mf * 16 + g + rs * 8;
            int bb = m >> 12, t = m & 4095;
            if (part == 0) {
                size_t base = ((size_t)(bb * HEADS + h) * NTOK + t) * HDIM;
                #pragma unroll
                for (int nf = 0; nf < 8; nf++) {
                    int d = nf * 8 + t4 * 2;
                    __half h0, l0, h1, l1;
                    split2(v[2 * nf], h0, l0);
                    split2(v[2 * nf + 1], h1, l1);
                    *(unsigned*)&g_qh[base + d] = pack2h(h0, h1);
                    *(unsigned*)&g_ql[base + d] = pack2h(l0, l1);
                }
            } else if (part == 1) {
                size_t base = ((size_t)(bb * HEADS + h) * NTOK + t) * HDIM;
                #pragma unroll
                for (int nf = 0; nf < 8; nf++) {
                    int d = nf * 8 + t4 * 2;
                    *(unsigned*)&g_kh[base + d] =
                        pack2h(__float2half(v[2 * nf]), __float2half(v[2 * nf + 1]));
                }
            } else {
                // V: transposed store [B,H,D,N], x2 split
                size_t vb = (size_t)(bb * HEADS + h) * HDIM * NTOK + t;
                #pragma unroll
                for (int nf = 0; nf < 8; nf++) {
                    int d = nf * 8 + t4 * 2;
                    __half h0, l0, h1, l1;
                    split2(v[2 * nf], h0, l0);
                    split2(v[2 * nf + 1], h1, l1);
                    g_vth[vb + (size_t)d * NTOK]       = h0;
                    g_vth[vb + (size_t)(d + 1) * NTOK] = h1;
                    g_vtl[vb + (size_t)d * NTOK]       = l0;
                    g_vtl[vb + (size_t)(d + 1) * NTOK] = l1;
                }
            }
        }
    }
}

// ---------------------------------------------------------------------------
// Flash attention (fp16, cp.async 2-stage, key tile 128, no online max).
// QK: Q x2 * K hi (2 MMAs). PV: P hi * V x2 (2 MMAs).
// Stage: [Kh 9216][Vth 8704][Vtl 8704] = 26624 elems.
// ---------------------------------------------------------------------------
#define KT 128
#define NKT (NTOK / KT)             // 32
#define FK (KT * STRF)              // 9216
#define FV (HDIM * VSTR)            // 8704
#define FSTAGE (FK + 2 * FV)        // 26624 elems = 53248 B

__global__ __launch_bounds__(256) void flash_mma_kernel()
{
    extern __shared__ __align__(16) __half fdyn[];

    const int tid = threadIdx.x;
    const int lane = tid & 31, wid = tid >> 5;
    const int g = lane >> 2, t4 = lane & 3;
    const int qb = blockIdx.x, bh = blockIdx.y;

    const size_t hbase = (size_t)bh * NTOK * HDIM;   // q/k [bh][t][d]
    const size_t vbase = (size_t)bh * HDIM * NTOK;   // vT  [bh][d][t]
    const int qrow = qb * 128 + wid * 16;

    // Q fragments (hi+lo) resident
    unsigned qh[4][4], ql[4][4];
    {
        const __half* Ph = g_qh + hbase + (size_t)qrow * HDIM;
        const __half* Pl = g_ql + hbase + (size_t)qrow * HDIM;
        #pragma unroll
        for (int ks = 0; ks < 4; ks++) {
            int c = ks * 16 + t4 * 2;
            qh[ks][0] = *(const unsigned*)&Ph[g * HDIM + c];
            qh[ks][1] = *(const unsigned*)&Ph[(g + 8) * HDIM + c];
            qh[ks][2] = *(const unsigned*)&Ph[g * HDIM + c + 8];
            qh[ks][3] = *(const unsigned*)&Ph[(g + 8) * HDIM + c + 8];
            ql[ks][0] = *(const unsigned*)&Pl[g * HDIM + c];
            ql[ks][1] = *(const unsigned*)&Pl[(g + 8) * HDIM + c];
            ql[ks][2] = *(const unsigned*)&Pl[g * HDIM + c + 8];
            ql[ks][3] = *(const unsigned*)&Pl[(g + 8) * HDIM + c + 8];
        }
    }

    float o[8][4];
    #pragma unroll
    for (int i = 0; i < 8; i++)
        #pragma unroll
        for (int c = 0; c < 4; c++) o[i][c] = 0.f;
    float lrow[2] = {0.f, 0.f};

    auto load_tile = [&](int kt, int buf) {
        __half* s = fdyn + buf * FSTAGE;
        size_t koff = hbase + (size_t)kt * KT * HDIM;
        size_t voff = vbase + (size_t)kt * KT;
        #pragma unroll
        for (int it = 0; it < 4; it++) {
            int idx = it * 256 + tid;
            int kr = idx >> 3, kc = (idx & 7) * 8;
            cpa16(&s[kr * STRF + kc], &g_kh[koff + (size_t)kr * HDIM + kc]);
            int vr = idx >> 4, vc = (idx & 15) * 8;
            cpa16(&s[FK + vr * VSTR + vc],      &g_vth[voff + (size_t)vr * NTOK + vc]);
            cpa16(&s[FK + FV + vr * VSTR + vc], &g_vtl[voff + (size_t)vr * NTOK + vc]);
        }
    };

    load_tile(0, 0);
    CPA_COMMIT();

    for (int kt = 0; kt < NKT; kt++) {
        __syncthreads();
        if (kt + 1 < NKT) load_tile(kt + 1, (kt + 1) & 1);
        CPA_COMMIT();
        CPA_WAIT1();
        __syncthreads();

        const __half* pKh = fdyn + (kt & 1) * FSTAGE;
        const __half* pVh = pKh + FK;
        const __half* pVl = pVh + FV;

        // S = Q K^T  (Q corrected, K truncated)
        float s[16][4];
        #pragma unroll
        for (int i = 0; i < 16; i++)
            #pragma unroll
            for (int c = 0; c < 4; c++) s[i][c] = 0.f;
        #pragma unroll
        for (int ks = 0; ks < 4; ks++) {
            #pragma unroll
            for (int nf = 0; nf < 16; nf++) {
                int base = (nf * 8 + g) * STRF + ks * 16 + t4 * 2;
                unsigned kbh[2] = {*(const unsigned*)&pKh[base], *(const unsigned*)&pKh[base + 8]};
                mma16816(s[nf], qh[ks], kbh);
                mma16816(s[nf], ql[ks], kbh);
            }
        }

        // P = exp2(S); per-thread l partials
        #pragma unroll
        for (int nf = 0; nf < 16; nf++) {
            float p0 = fex2(s[nf][0]);
            float p1 = fex2(s[nf][1]);
            float p2 = fex2(s[nf][2]);
            float p3 = fex2(s[nf][3]);
            s[nf][0] = p0; s[nf][1] = p1; s[nf][2] = p2; s[nf][3] = p3;
            lrow[0] += p0 + p1;
            lrow[1] += p2 + p3;
        }

        // O += P V  (P truncated to fp16, V corrected x2)
        #pragma unroll
        for (int ks = 0; ks < 8; ks++) {
            unsigned pah[4];
            pah[0] = pack2h(__float2half(s[2 * ks][0]),     __float2half(s[2 * ks][1]));
            pah[1] = pack2h(__float2half(s[2 * ks][2]),     __float2half(s[2 * ks][3]));
            pah[2] = pack2h(__float2half(s[2 * ks + 1][0]), __float2half(s[2 * ks + 1][1]));
            pah[3] = pack2h(__float2half(s[2 * ks + 1][2]), __float2half(s[2 * ks + 1][3]));
            #pragma unroll
            for (int nfd = 0; nfd < 8; nfd++) {
                int n = nfd * 8 + g;
                int k0 = ks * 16 + t4 * 2;
                unsigned vbh[2] = {*(const unsigned*)&pVh[n * VSTR + k0],
                                   *(const unsigned*)&pVh[n * VSTR + k0 + 8]};
                unsigned vbl[2] = {*(const unsigned*)&pVl[n * VSTR + k0],
                                   *(const unsigned*)&pVl[n * VSTR + k0 + 8]};
                mma16816(o[nfd], pah, vbh);
                mma16816(o[nfd], pah, vbl);
            }
        }
    }

    lrow[0] += __shfl_xor_sync(0xffffffffu, lrow[0], 1, 4);
    lrow[0] += __shfl_xor_sync(0xffffffffu, lrow[0], 2, 4);
    lrow[1] += __shfl_xor_sync(0xffffffffu, lrow[1], 1, 4);
    lrow[1] += __shfl_xor_sync(0xffffffffu, lrow[1], 2, 4);

    const int bb = bh >> 4, hh = bh & 15;
    #pragma unroll
    for (int rs = 0; rs < 2; rs++) {
        float inv = 1.0f / lrow[rs];
        int t = qrow + g + rs * 8;
        size_t base = ((size_t)(bb * NTOK + t)) * CDIM + hh * HDIM;
        #pragma unroll
        for (int nfd = 0; nfd < 8; nfd++) {
            int d = nfd * 8 + t4 * 2;
            __half h0, l0, h1, l1;
            split2(o[nfd][rs * 2] * inv, h0, l0);
            split2(o[nfd][rs * 2 + 1] * inv, h1, l1);
            *(unsigned*)&g_oh[base + d] = pack2h(h0, h1);
            *(unsigned*)&g_ol[base + d] = pack2h(l0, l1);
        }
    }
}

// ---------------------------------------------------------------------------
// Output projection GEMM (fp16 x2, cp.async 2-stage) + bias -> fp32 d_out
// ---------------------------------------------------------------------------
__global__ __launch_bounds__(256, 2) void proj_mma_kernel(
    const float* __restrict__ bias, float* __restrict__ out)
{
    extern __shared__ __align__(16) __half dyn[];

    const int tid = threadIdx.x;
    const int lane = tid & 31, wid = tid >> 5;
    const int wm = wid & 3, wn = wid >> 2;
    const int g = lane >> 2, t4 = lane & 3;
    const int row0 = blockIdx.y * 128;
    const int col0 = blockIdx.x * 128;

    const int lr0 = tid >> 2, lc0 = (tid & 3) * 8;
    const int lr1 = (256 + tid) >> 2, lc1 = lc0;

    float acc[2][8][4];
    #pragma unroll
    for (int i = 0; i < 2; i++)
        #pragma unroll
        for (int j = 0; j < 8; j++)
            #pragma unroll
            for (int c = 0; c < 4; c++) acc[i][j][c] = 0.f;

    auto load_stage = [&](int kt, int st) {
        __half* s = dyn + st * GSTAGE;
        int k0 = kt * 32;
        cpa16(&s[0 * GSTG + lr0 * STR + lc0], &g_oh [(size_t)(row0 + lr0) * CDIM + k0 + lc0]);
        cpa16(&s[0 * GSTG + lr1 * STR + lc1], &g_oh [(size_t)(row0 + lr1) * CDIM + k0 + lc1]);
        cpa16(&s[1 * GSTG + lr0 * STR + lc0], &g_ol [(size_t)(row0 + lr0) * CDIM + k0 + lc0]);
        cpa16(&s[1 * GSTG + lr1 * STR + lc1], &g_ol [(size_t)(row0 + lr1) * CDIM + k0 + lc1]);
        cpa16(&s[2 * GSTG + lr0 * STR + lc0], &g_wph[(size_t)(col0 + lr0) * CDIM + k0 + lc0]);
        cpa16(&s[2 * GSTG + lr1 * STR + lc1], &g_wph[(size_t)(col0 + lr1) * CDIM + k0 + lc1]);
    };

    load_stage(0, 0);
    CPA_COMMIT();

    for (int kt = 0; kt < CDIM / 32; kt++) {
        __syncthreads();
        if (kt + 1 < CDIM / 32) load_stage(kt + 1, (kt + 1) & 1);
        CPA_COMMIT();
        CPA_WAIT1();
        __syncthreads();

        const __half* pAh = dyn + (kt & 1) * GSTAGE;
        const __half* pAl = pAh + GSTG;
        const __half* pBh = pAl + GSTG;

        #pragma unroll
        for (int ks = 0; ks < 2; ks++) {
            unsigned ah[2][4], al[2][4];
            #pragma unroll
            for (int mf = 0; mf < 2; mf++) {
                int base = (wm * 32 + mf * 16 + g) * STR + ks * 16 + t4 * 2;
                ah[mf][0] = *(const unsigned*)&pAh[base];
                ah[mf][1] = *(const unsigned*)&pAh[base + 8 * STR];
                ah[mf][2] = *(const unsigned*)&pAh[base + 8];
                ah[mf][3] = *(const unsigned*)&pAh[base + 8 * STR + 8];
                al[mf][0] = *(const unsigned*)&pAl[base];
                al[mf][1] = *(const unsigned*)&pAl[base + 8 * STR];
                al[mf][2] = *(const unsigned*)&pAl[base + 8];
                al[mf][3] = *(const unsigned*)&pAl[base + 8 * STR + 8];
            }
            #pragma unroll
            for (int nf = 0; nf < 8; nf++) {
                int base = (wn * 64 + nf * 8 + g) * STR + ks * 16 + t4 * 2;
                unsigned bh[2] = {*(const unsigned*)&pBh[base], *(const unsigned*)&pBh[base + 8]};
                #pragma unroll
                for (int mf = 0; mf < 2; mf++) {
                    mma16816(acc[mf][nf], ah[mf], bh);
                    mma16816(acc[mf][nf], al[mf], bh);
                }
            }
        }
    }

    const int wcol0 = col0 + wn * 64;
    #pragma unroll
    for (int mf = 0; mf < 2; mf++) {
        #pragma unroll
        for (int rs = 0; rs < 2; rs++) {
            int m = row0 + wm * 32 + mf * 16 + g + rs * 8;
            #pragma unroll
            for (int nf = 0; nf < 8; nf++) {
                int c = wcol0 + nf * 8 + t4 * 2;
                float2 r;
                r.x = acc[mf][nf][rs * 2]     + bias[c];
                r.y = acc[mf][nf][rs * 2 + 1] + bias[c + 1];
                *(float2*)&out[(size_t)m * CDIM + c] = r;
            }
        }
    }
}

// ---------------------------------------------------------------------------
extern "C" void kernel_launch(void* const* d_in, const int* in_sizes, int n_in,
                              void* d_out, int out_size)
{
    const float* x      = (const float*)d_in[0];
    const float* qkv_w  = (const float*)d_in[1];
    const float* qkv_b  = (const float*)d_in[2];
    const float* qnw    = (const float*)d_in[3];
    const float* qnb    = (const float*)d_in[4];
    const float* knw    = (const float*)d_in[5];
    const float* knb    = (const float*)d_in[6];
    const float* proj_w = (const float*)d_in[7];
    const float* pb     = (const float*)d_in[8];
    float* out = (float*)d_out;

    const int gsmem = 2 * GSTAGE * (int)sizeof(__half);   // 61440
    const int fsmem = 2 * FSTAGE * (int)sizeof(__half);   // 106496
    static int attr_done = 0;
    if (!attr_done) {
        cudaFuncSetAttribute(qkv_mma_kernel,  cudaFuncAttributeMaxDynamicSharedMemorySize, gsmem);
        cudaFuncSetAttribute(proj_mma_kernel, cudaFuncAttributeMaxDynamicSharedMemorySize, gsmem);
        cudaFuncSetAttribute(flash_mma_kernel, cudaFuncAttributeMaxDynamicSharedMemorySize, fsmem);
        attr_done = 1;
    }

    convert_kernel<<<2048, 256>>>(x, 0, MROWS * CDIM);
    convert_kernel<<<1024, 256>>>(qkv_w, 1, QKVN * CDIM);
    convert_kernel<<<512, 256>>>(proj_w, 2, CDIM * CDIM);

    qkv_mma_kernel<<<dim3(QKVN / 128, MROWS / 128), 256, gsmem>>>(qkv_b, qnw, qnb, knw, knb);
    flash_mma_kernel<<<dim3(NTOK / 128, BATCH * HEADS), 256, fsmem>>>();
    proj_mma_kernel<<<dim3(CDIM / 128, MROWS / 128), 256, gsmem>>>(pb, out);
}